// round 1
// baseline (speedup 1.0000x reference)
#include <cuda_runtime.h>
#include <math.h>

#define SEQ    2048
#define HDIM   1024
#define NH     16
#define HS     64
#define MTOT   4096            // B*S
#define N_QKV  3072            // 3*HDIM

// Scratch (allocation-free rule: device globals)
__device__ float g_qkv[(size_t)MTOT * N_QKV];   // [4096, 3072] : q | k | v
__device__ float g_ao [(size_t)MTOT * HDIM];    // attention output [4096, 1024]

// ---------------------------------------------------------------------------
// GEMM: C[M,N] = A'[M,K] @ B[K,N], where A' = A + pos (broadcast over batch)
// for output columns n < pos_ncut, else A' = A. 128x128x16 tile, 256 threads,
// 8x8 per-thread microtile. M,N,K multiples of 128/128/16 (guaranteed here).
// ---------------------------------------------------------------------------
__global__ __launch_bounds__(256, 2)
void gemm_kernel(const float* __restrict__ A,
                 const float* __restrict__ pos,   // may be null
                 const float* __restrict__ B,
                 float* __restrict__ C,
                 int N, int K, int pos_ncut)
{
    __shared__ float As[16][132];   // transposed: As[k][m]
    __shared__ float Bs[16][132];   // Bs[k][n]

    const int tid = threadIdx.x;
    const int m0  = blockIdx.y * 128;
    const int n0  = blockIdx.x * 128;
    const bool addpos = (pos != nullptr) && (n0 < pos_ncut);

    const int r0 = (tid >> 4) * 8;
    const int c0 = (tid & 15) * 8;

    float acc[8][8];
    #pragma unroll
    for (int i = 0; i < 8; i++)
        #pragma unroll
        for (int j = 0; j < 8; j++)
            acc[i][j] = 0.0f;

    for (int k0 = 0; k0 < K; k0 += 16) {
        // ---- load A tile (128 x 16), store transposed ----
        #pragma unroll
        for (int it = 0; it < 2; it++) {
            int f   = tid + it * 256;       // 0..511 float4s
            int row = f >> 2;               // 0..127
            int c4  = (f & 3) << 2;         // 0,4,8,12
            float4 a = *(const float4*)(A + (size_t)(m0 + row) * K + k0 + c4);
            if (addpos) {
                float4 p = *(const float4*)(pos + (size_t)((m0 + row) & (SEQ - 1)) * K + k0 + c4);
                a.x += p.x; a.y += p.y; a.z += p.z; a.w += p.w;
            }
            As[c4 + 0][row] = a.x;
            As[c4 + 1][row] = a.y;
            As[c4 + 2][row] = a.z;
            As[c4 + 3][row] = a.w;
        }
        // ---- load B tile (16 x 128) ----
        #pragma unroll
        for (int it = 0; it < 2; it++) {
            int f  = tid + it * 256;        // 0..511 float4s
            int kr = f >> 5;                // 0..15
            int c4 = (f & 31) << 2;         // 0..124
            float4 b = *(const float4*)(B + (size_t)(k0 + kr) * N + n0 + c4);
            *(float4*)&Bs[kr][c4] = b;
        }
        __syncthreads();

        #pragma unroll
        for (int kk = 0; kk < 16; kk++) {
            float4 a0 = *(const float4*)&As[kk][r0];
            float4 a1 = *(const float4*)&As[kk][r0 + 4];
            float4 b0 = *(const float4*)&Bs[kk][c0];
            float4 b1 = *(const float4*)&Bs[kk][c0 + 4];
            float a[8] = {a0.x, a0.y, a0.z, a0.w, a1.x, a1.y, a1.z, a1.w};
            float b[8] = {b0.x, b0.y, b0.z, b0.w, b1.x, b1.y, b1.z, b1.w};
            #pragma unroll
            for (int i = 0; i < 8; i++)
                #pragma unroll
                for (int j = 0; j < 8; j++)
                    acc[i][j] += a[i] * b[j];
        }
        __syncthreads();
    }

    #pragma unroll
    for (int i = 0; i < 8; i++) {
        float* cp = C + (size_t)(m0 + r0 + i) * N + n0 + c0;
        *(float4*)(cp)     = make_float4(acc[i][0], acc[i][1], acc[i][2], acc[i][3]);
        *(float4*)(cp + 4) = make_float4(acc[i][4], acc[i][5], acc[i][6], acc[i][7]);
    }
}

// ---------------------------------------------------------------------------
// Flash attention (causal), fp32. One CTA = one (b, h, 128-query tile).
// K-tiles of 128 keys. Online softmax. 256 threads.
// smem: Qst[64][132] (d-major), Kst[64][132], Vs[128][68], Ps[128][132],
//       red[128][17]. Total 178688 bytes.
// ---------------------------------------------------------------------------
#define ATTN_SMEM_FLOATS (64*132 + 64*132 + 128*68 + 128*132 + 128*17)

__global__ __launch_bounds__(256, 1)
void attn_kernel(const float* __restrict__ qkv, float* __restrict__ ao)
{
    extern __shared__ float sm[];
    float* Qst = sm;                     // 64*132
    float* Kst = Qst + 64 * 132;         // 64*132
    float* Vs  = Kst + 64 * 132;         // 128*68
    float* Ps  = Vs  + 128 * 68;         // 128*132
    float* red = Ps  + 128 * 132;        // 128*17

    const int tid = threadIdx.x;
    const int tr  = tid >> 4;            // 0..15
    const int tc  = tid & 15;            // 0..15
    const int r0  = tr * 8;
    const int c0  = tc * 8;
    const int d0  = tc * 4;

    const int bh = blockIdx.y;           // 0..31
    const int b  = bh >> 4;
    const int h  = bh & 15;
    const int qt = (int)gridDim.x - 1 - (int)blockIdx.x;   // reverse: long tiles first

    const size_t rs = N_QKV;
    const float* qbase = qkv + (size_t)(b * SEQ + qt * 128) * rs + h * HS;

    // ---- load Q tile transposed (d-major) ----
    #pragma unroll
    for (int it = 0; it < 8; it++) {
        int f   = tid + it * 256;        // 0..2047 float4s
        int row = f >> 4;                // 0..127
        int c4  = (f & 15) << 2;         // 0..60
        float4 v = *(const float4*)(qbase + (size_t)row * rs + c4);
        Qst[(c4 + 0) * 132 + row] = v.x;
        Qst[(c4 + 1) * 132 + row] = v.y;
        Qst[(c4 + 2) * 132 + row] = v.z;
        Qst[(c4 + 3) * 132 + row] = v.w;
    }

    float m_run[8], l_run[8], o[8][4];
    #pragma unroll
    for (int i = 0; i < 8; i++) {
        m_run[i] = -1e30f;
        l_run[i] = 0.0f;
        o[i][0] = o[i][1] = o[i][2] = o[i][3] = 0.0f;
    }

    const float scale = 0.125f;          // 1/sqrt(64)

    for (int kt = 0; kt <= qt; kt++) {
        __syncthreads();   // Qst ready (iter 0); prev PV done (later iters)

        const float* kbase = qkv + (size_t)(b * SEQ + kt * 128) * rs + HDIM + h * HS;
        const float* vbase = kbase + HDIM;
        #pragma unroll
        for (int it = 0; it < 8; it++) {
            int f   = tid + it * 256;
            int row = f >> 4;
            int c4  = (f & 15) << 2;
            float4 kv = *(const float4*)(kbase + (size_t)row * rs + c4);
            Kst[(c4 + 0) * 132 + row] = kv.x;
            Kst[(c4 + 1) * 132 + row] = kv.y;
            Kst[(c4 + 2) * 132 + row] = kv.z;
            Kst[(c4 + 3) * 132 + row] = kv.w;
            float4 vv = *(const float4*)(vbase + (size_t)row * rs + c4);
            *(float4*)&Vs[row * 68 + c4] = vv;
        }
        __syncthreads();

        // ---- scores: S = Q @ K^T (128 x 128), inner dim 64 ----
        float acc[8][8];
        #pragma unroll
        for (int i = 0; i < 8; i++)
            #pragma unroll
            for (int j = 0; j < 8; j++)
                acc[i][j] = 0.0f;

        #pragma unroll 8
        for (int d = 0; d < 64; d++) {
            float4 a0 = *(const float4*)&Qst[d * 132 + r0];
            float4 a1 = *(const float4*)&Qst[d * 132 + r0 + 4];
            float4 b0 = *(const float4*)&Kst[d * 132 + c0];
            float4 b1 = *(const float4*)&Kst[d * 132 + c0 + 4];
            float a[8] = {a0.x, a0.y, a0.z, a0.w, a1.x, a1.y, a1.z, a1.w};
            float bb[8] = {b0.x, b0.y, b0.z, b0.w, b1.x, b1.y, b1.z, b1.w};
            #pragma unroll
            for (int i = 0; i < 8; i++)
                #pragma unroll
                for (int j = 0; j < 8; j++)
                    acc[i][j] += a[i] * bb[j];
        }

        // ---- scale + causal mask (only diagonal tile needs it) ----
        if (kt == qt) {
            #pragma unroll
            for (int i = 0; i < 8; i++)
                #pragma unroll
                for (int j = 0; j < 8; j++)
                    acc[i][j] = ((c0 + j) > (r0 + i)) ? -1e30f : acc[i][j] * scale;
        } else {
            #pragma unroll
            for (int i = 0; i < 8; i++)
                #pragma unroll
                for (int j = 0; j < 8; j++)
                    acc[i][j] *= scale;
        }

        // ---- row max (per-thread, then cross-tc via smem) ----
        #pragma unroll
        for (int i = 0; i < 8; i++) {
            float rm = acc[i][0];
            #pragma unroll
            for (int j = 1; j < 8; j++) rm = fmaxf(rm, acc[i][j]);
            red[(r0 + i) * 17 + tc] = rm;
        }
        __syncthreads();

        float nm[8], fac[8];
        #pragma unroll
        for (int i = 0; i < 8; i++) {
            float tm = red[(r0 + i) * 17];
            #pragma unroll
            for (int t = 1; t < 16; t++) tm = fmaxf(tm, red[(r0 + i) * 17 + t]);
            nm[i]  = fmaxf(m_run[i], tm);
            fac[i] = __expf(m_run[i] - nm[i]);
        }

        // ---- exponentiate + row sums ----
        float rsum[8];
        #pragma unroll
        for (int i = 0; i < 8; i++) {
            float s = 0.0f;
            #pragma unroll
            for (int j = 0; j < 8; j++) {
                float p = __expf(acc[i][j] - nm[i]);
                acc[i][j] = p;
                s += p;
            }
            rsum[i] = s;
        }
        __syncthreads();   // all reads of red(max) done before reuse
        #pragma unroll
        for (int i = 0; i < 8; i++)
            red[(r0 + i) * 17 + tc] = rsum[i];
        __syncthreads();

        #pragma unroll
        for (int i = 0; i < 8; i++) {
            float ts = 0.0f;
            #pragma unroll
            for (int t = 0; t < 16; t++) ts += red[(r0 + i) * 17 + t];
            l_run[i] = l_run[i] * fac[i] + ts;
            m_run[i] = nm[i];
            o[i][0] *= fac[i]; o[i][1] *= fac[i];
            o[i][2] *= fac[i]; o[i][3] *= fac[i];
        }

        // ---- stage P to smem ----
        #pragma unroll
        for (int i = 0; i < 8; i++) {
            *(float4*)&Ps[(r0 + i) * 132 + c0]     = make_float4(acc[i][0], acc[i][1], acc[i][2], acc[i][3]);
            *(float4*)&Ps[(r0 + i) * 132 + c0 + 4] = make_float4(acc[i][4], acc[i][5], acc[i][6], acc[i][7]);
        }
        __syncthreads();

        // ---- O += P @ V (128 x 64, inner 128) ----
        #pragma unroll 4
        for (int k4 = 0; k4 < 128; k4 += 4) {
            float4 v0 = *(const float4*)&Vs[(k4 + 0) * 68 + d0];
            float4 v1 = *(const float4*)&Vs[(k4 + 1) * 68 + d0];
            float4 v2 = *(const float4*)&Vs[(k4 + 2) * 68 + d0];
            float4 v3 = *(const float4*)&Vs[(k4 + 3) * 68 + d0];
            #pragma unroll
            for (int i = 0; i < 8; i++) {
                float4 p = *(const float4*)&Ps[(r0 + i) * 132 + k4];
                o[i][0] += p.x * v0.x + p.y * v1.x + p.z * v2.x + p.w * v3.x;
                o[i][1] += p.x * v0.y + p.y * v1.y + p.z * v2.y + p.w * v3.y;
                o[i][2] += p.x * v0.z + p.y * v1.z + p.z * v2.z + p.w * v3.z;
                o[i][3] += p.x * v0.w + p.y * v1.w + p.z * v2.w + p.w * v3.w;
            }
        }
    }

    // ---- normalize and write out: ao[b, q, h*64 + d] ----
    float* aobase = ao + (size_t)(b * SEQ + qt * 128) * HDIM + h * HS;
    #pragma unroll
    for (int i = 0; i < 8; i++) {
        float inv = 1.0f / l_run[i];
        *(float4*)(aobase + (size_t)(r0 + i) * HDIM + d0) =
            make_float4(o[i][0] * inv, o[i][1] * inv, o[i][2] * inv, o[i][3] * inv);
    }
}

// ---------------------------------------------------------------------------
extern "C" void kernel_launch(void* const* d_in, const int* in_sizes, int n_in,
                              void* d_out, int out_size)
{
    const float* x    = (const float*)d_in[0];   // [2, 2048, 1024]
    const float* pos  = (const float*)d_in[1];   // [2048, 1024]
    const float* Wqkv = (const float*)d_in[2];   // [1024, 3072]
    const float* Wout = (const float*)d_in[3];   // [1024, 1024]
    float* out = (float*)d_out;                  // [2, 2048, 1024]

    float *qkv_p, *ao_p;
    cudaGetSymbolAddress((void**)&qkv_p, g_qkv);
    cudaGetSymbolAddress((void**)&ao_p,  g_ao);

    // 1) qkv = [(x+pos) @ Wqkv[:, :2H] | x @ Wqkv[:, 2H:]]
    {
        dim3 grid(N_QKV / 128, MTOT / 128);
        gemm_kernel<<<grid, 256>>>(x, pos, Wqkv, qkv_p, N_QKV, HDIM, 2 * HDIM);
    }

    // 2) flash attention
    {
        int smem_bytes = ATTN_SMEM_FLOATS * (int)sizeof(float);   // 178688
        cudaFuncSetAttribute(attn_kernel,
                             cudaFuncAttributeMaxDynamicSharedMemorySize, smem_bytes);
        dim3 grid(SEQ / 128, 2 * NH);
        attn_kernel<<<grid, 256, smem_bytes>>>(qkv_p, ao_p);
    }

    // 3) out = ao @ Wout
    {
        dim3 grid(HDIM / 128, MTOT / 128);
        gemm_kernel<<<grid, 256>>>(ao_p, nullptr, Wout, out, HDIM, HDIM, 0);
    }
}

// round 2
// speedup vs baseline: 2.3726x; 2.3726x over previous
#include <cuda_runtime.h>
#include <math.h>
#include <stdint.h>

#define SEQ    2048
#define HDIM   1024
#define NH     16
#define HS     64
#define MTOT   4096            // B*S
#define N_QKV  3072            // 3*HDIM

// Scratch (allocation-free rule: device globals)
__device__ float g_qkv[(size_t)MTOT * N_QKV];   // [4096, 3072] : q | k | v
__device__ float g_ao [(size_t)MTOT * HDIM];    // attention output [4096, 1024]

// ---------------------------------------------------------------------------
// helpers
// ---------------------------------------------------------------------------
__device__ __forceinline__ uint32_t f2tf(float x) {
    uint32_t u;
    asm("cvt.rna.tf32.f32 %0, %1;" : "=r"(u) : "f"(x));
    return u;
}
__device__ __forceinline__ uint4 f2tf4(float4 a) {
    uint4 u;
    u.x = f2tf(a.x); u.y = f2tf(a.y); u.z = f2tf(a.z); u.w = f2tf(a.w);
    return u;
}

#define MMA8(d, a, b)                                                          \
    asm volatile(                                                              \
        "mma.sync.aligned.m16n8k8.row.col.f32.tf32.tf32.f32 "                  \
        "{%0,%1,%2,%3},{%4,%5,%6,%7},{%8,%9},{%0,%1,%2,%3};"                   \
        : "+f"((d)[0]), "+f"((d)[1]), "+f"((d)[2]), "+f"((d)[3])               \
        : "r"((a)[0]), "r"((a)[1]), "r"((a)[2]), "r"((a)[3]),                  \
          "r"((b)[0]), "r"((b)[1]))

// ---------------------------------------------------------------------------
// tf32 GEMM: C[M,N] = A'[M,K] @ B[K,N]; A' = A + pos for n-block < pos_ncut.
// 128x128x32 tile, 256 threads (8 warps), warp tile 64x32 (4 m-frags, 4 n-frags).
// As row-major [128][36] (bank = 4r+c, conflict-free frag loads),
// Bs k-major   [32][132] (bank = 4k+n, conflict-free frag loads).
// ---------------------------------------------------------------------------
__global__ __launch_bounds__(256, 2)
void gemm_tf32(const float* __restrict__ A,
               const float* __restrict__ pos,
               const float* __restrict__ B,
               float* __restrict__ C,
               int N, int K, int pos_ncut)
{
    __shared__ uint32_t As[128 * 36];
    __shared__ uint32_t Bs[32 * 132];

    const int tid  = threadIdx.x;
    const int lane = tid & 31;
    const int warp = tid >> 5;
    const int wm   = warp >> 2;          // 0..1
    const int wn   = warp & 3;           // 0..3
    const int g    = lane >> 2;          // 0..7
    const int t    = lane & 3;           // 0..3

    const int m0 = blockIdx.y * 128;
    const int n0 = blockIdx.x * 128;
    const bool addpos = (pos != nullptr) && (n0 < pos_ncut);

    float acc[4][4][4];
    #pragma unroll
    for (int i = 0; i < 4; i++)
        #pragma unroll
        for (int j = 0; j < 4; j++)
            #pragma unroll
            for (int c = 0; c < 4; c++)
                acc[i][j][c] = 0.0f;

    for (int k0 = 0; k0 < K; k0 += 32) {
        // A tile: 128x32 -> 1024 float4
        #pragma unroll
        for (int it = 0; it < 4; it++) {
            int f   = tid + it * 256;
            int row = f >> 3;
            int c4  = (f & 7) << 2;
            float4 a = *(const float4*)(A + (size_t)(m0 + row) * K + k0 + c4);
            if (addpos) {
                float4 p = *(const float4*)(pos + (size_t)((m0 + row) & (SEQ - 1)) * K + k0 + c4);
                a.x += p.x; a.y += p.y; a.z += p.z; a.w += p.w;
            }
            *(uint4*)&As[row * 36 + c4] = f2tf4(a);
        }
        // B tile: 32x128 -> 1024 float4
        #pragma unroll
        for (int it = 0; it < 4; it++) {
            int f  = tid + it * 256;
            int kr = f >> 5;
            int c4 = (f & 31) << 2;
            float4 b = *(const float4*)(B + (size_t)(k0 + kr) * N + n0 + c4);
            *(uint4*)&Bs[kr * 132 + c4] = f2tf4(b);
        }
        __syncthreads();

        #pragma unroll
        for (int ks = 0; ks < 4; ks++) {
            uint32_t afr[4][4], bfr[4][2];
            #pragma unroll
            for (int mi = 0; mi < 4; mi++) {
                int r = wm * 64 + mi * 16 + g;
                afr[mi][0] = As[r * 36 + ks * 8 + t];
                afr[mi][1] = As[(r + 8) * 36 + ks * 8 + t];
                afr[mi][2] = As[r * 36 + ks * 8 + t + 4];
                afr[mi][3] = As[(r + 8) * 36 + ks * 8 + t + 4];
            }
            #pragma unroll
            for (int ni = 0; ni < 4; ni++) {
                int n = wn * 32 + ni * 8 + g;
                bfr[ni][0] = Bs[(ks * 8 + t) * 132 + n];
                bfr[ni][1] = Bs[(ks * 8 + t + 4) * 132 + n];
            }
            #pragma unroll
            for (int mi = 0; mi < 4; mi++)
                #pragma unroll
                for (int ni = 0; ni < 4; ni++)
                    MMA8(acc[mi][ni], afr[mi], bfr[ni]);
        }
        __syncthreads();
    }

    // epilogue: c0,c1 at (g, 2t..2t+1), c2,c3 at (g+8, ...)
    #pragma unroll
    for (int mi = 0; mi < 4; mi++) {
        int row = m0 + wm * 64 + mi * 16 + g;
        #pragma unroll
        for (int ni = 0; ni < 4; ni++) {
            int col = n0 + wn * 32 + ni * 8 + 2 * t;
            *(float2*)(C + (size_t)row * N + col)       = make_float2(acc[mi][ni][0], acc[mi][ni][1]);
            *(float2*)(C + (size_t)(row + 8) * N + col) = make_float2(acc[mi][ni][2], acc[mi][ni][3]);
        }
    }
}

// ---------------------------------------------------------------------------
// Flash attention (causal), tf32 mma + fp32 softmax.
// CTA = (b, h, 128-q-rows). 256 threads, warp w owns q-rows [16w, 16w+16).
// smem (uint/tf32): uQ[128][68] row-major (pre-scaled by 1/8),
//                   uK[64][132] d-major, uV[128][68] row-major,
//                   uP[128][132] row-major.
// ---------------------------------------------------------------------------
#define ATTN_SMEM_BYTES ((128*68 + 64*132 + 128*68 + 128*132) * 4)

__global__ __launch_bounds__(256, 1)
void attn_tf32(const float* __restrict__ qkv, float* __restrict__ ao)
{
    extern __shared__ uint32_t usm[];
    uint32_t* uQ = usm;                  // 128*68
    uint32_t* uK = uQ + 128 * 68;        // 64*132
    uint32_t* uV = uK + 64 * 132;        // 128*68
    uint32_t* uP = uV + 128 * 68;        // 128*132

    const int tid  = threadIdx.x;
    const int lane = tid & 31;
    const int warp = tid >> 5;
    const int g    = lane >> 2;          // 0..7
    const int t    = lane & 3;           // 0..3
    const int q0   = warp * 16;

    const int bh = blockIdx.y;
    const int b  = bh >> 4;
    const int h  = bh & 15;
    const int qt = (int)gridDim.x - 1 - (int)blockIdx.x;

    const size_t rs = N_QKV;
    const float* qbase = qkv + (size_t)(b * SEQ + qt * 128) * rs + h * HS;

    // ---- load Q (scaled by 1/sqrt(64)) row-major ----
    #pragma unroll
    for (int it = 0; it < 8; it++) {
        int f   = tid + it * 256;
        int row = f >> 4;
        int c4  = (f & 15) << 2;
        float4 v = *(const float4*)(qbase + (size_t)row * rs + c4);
        v.x *= 0.125f; v.y *= 0.125f; v.z *= 0.125f; v.w *= 0.125f;
        *(uint4*)&uQ[row * 68 + c4] = f2tf4(v);
    }

    float m0r = -1e30f, m1r = -1e30f, l0r = 0.0f, l1r = 0.0f;
    float o[8][4];
    #pragma unroll
    for (int ni = 0; ni < 8; ni++)
        o[ni][0] = o[ni][1] = o[ni][2] = o[ni][3] = 0.0f;

    for (int kt = 0; kt <= qt; kt++) {
        __syncthreads();   // Q ready (first iter) / prev PV reads of uV done

        const float* kbase = qkv + (size_t)(b * SEQ + kt * 128) * rs + HDIM + h * HS;
        const float* vbase = kbase + HDIM;

        // ---- K: load [key][d], store transposed uK[d][key] (2-way STS max) ----
        #pragma unroll
        for (int it = 0; it < 8; it++) {
            int key = (lane >> 2) + 8 * ((it & 1) + 2 * warp);
            int c4  = (lane & 3) * 4 + (it >> 1) * 16;
            float4 kv = *(const float4*)(kbase + (size_t)key * rs + c4);
            uK[(c4 + 0) * 132 + key] = f2tf(kv.x);
            uK[(c4 + 1) * 132 + key] = f2tf(kv.y);
            uK[(c4 + 2) * 132 + key] = f2tf(kv.z);
            uK[(c4 + 3) * 132 + key] = f2tf(kv.w);
        }
        // ---- V: row-major, coalesced, conflict-free ----
        #pragma unroll
        for (int it = 0; it < 8; it++) {
            int f   = tid + it * 256;
            int row = f >> 4;
            int c4  = (f & 15) << 2;
            float4 vv = *(const float4*)(vbase + (size_t)row * rs + c4);
            *(uint4*)&uV[row * 68 + c4] = f2tf4(vv);
        }
        __syncthreads();

        // ---- S = Q @ K^T : per warp m16 x n128 x k64 ----
        float sacc[16][4];
        #pragma unroll
        for (int ni = 0; ni < 16; ni++)
            sacc[ni][0] = sacc[ni][1] = sacc[ni][2] = sacc[ni][3] = 0.0f;

        #pragma unroll
        for (int ks = 0; ks < 8; ks++) {
            uint32_t afr[4];
            afr[0] = uQ[(q0 + g) * 68 + ks * 8 + t];
            afr[1] = uQ[(q0 + g + 8) * 68 + ks * 8 + t];
            afr[2] = uQ[(q0 + g) * 68 + ks * 8 + t + 4];
            afr[3] = uQ[(q0 + g + 8) * 68 + ks * 8 + t + 4];
            #pragma unroll
            for (int ni = 0; ni < 16; ni++) {
                uint32_t bfr[2];
                bfr[0] = uK[(ks * 8 + t) * 132 + ni * 8 + g];
                bfr[1] = uK[(ks * 8 + t + 4) * 132 + ni * 8 + g];
                MMA8(sacc[ni], afr, bfr);
            }
        }

        // ---- causal mask on diagonal tile ----
        const int r0l = q0 + g, r1l = r0l + 8;
        if (kt == qt) {
            #pragma unroll
            for (int ni = 0; ni < 16; ni++) {
                int c = ni * 8 + 2 * t;
                if (c     > r0l) sacc[ni][0] = -1e30f;
                if (c + 1 > r0l) sacc[ni][1] = -1e30f;
                if (c     > r1l) sacc[ni][2] = -1e30f;
                if (c + 1 > r1l) sacc[ni][3] = -1e30f;
            }
        }

        // ---- row max (quad reduce) ----
        float rm0 = -1e30f, rm1 = -1e30f;
        #pragma unroll
        for (int ni = 0; ni < 16; ni++) {
            rm0 = fmaxf(rm0, fmaxf(sacc[ni][0], sacc[ni][1]));
            rm1 = fmaxf(rm1, fmaxf(sacc[ni][2], sacc[ni][3]));
        }
        rm0 = fmaxf(rm0, __shfl_xor_sync(0xffffffffu, rm0, 1));
        rm0 = fmaxf(rm0, __shfl_xor_sync(0xffffffffu, rm0, 2));
        rm1 = fmaxf(rm1, __shfl_xor_sync(0xffffffffu, rm1, 1));
        rm1 = fmaxf(rm1, __shfl_xor_sync(0xffffffffu, rm1, 2));

        float nm0 = fmaxf(m0r, rm0), nm1 = fmaxf(m1r, rm1);
        float fac0 = __expf(m0r - nm0), fac1 = __expf(m1r - nm1);

        __syncwarp();   // previous PV loads of uP finished before overwrite

        // ---- exp, row sums, stage P (tf32) ----
        float rs0 = 0.0f, rs1 = 0.0f;
        #pragma unroll
        for (int ni = 0; ni < 16; ni++) {
            float p00 = __expf(sacc[ni][0] - nm0);
            float p01 = __expf(sacc[ni][1] - nm0);
            float p10 = __expf(sacc[ni][2] - nm1);
            float p11 = __expf(sacc[ni][3] - nm1);
            rs0 += p00 + p01;
            rs1 += p10 + p11;
            int c = ni * 8 + 2 * t;
            uint2 u0; u0.x = f2tf(p00); u0.y = f2tf(p01);
            uint2 u1; u1.x = f2tf(p10); u1.y = f2tf(p11);
            *(uint2*)&uP[(q0 + g) * 132 + c]     = u0;
            *(uint2*)&uP[(q0 + g + 8) * 132 + c] = u1;
        }
        rs0 += __shfl_xor_sync(0xffffffffu, rs0, 1);
        rs0 += __shfl_xor_sync(0xffffffffu, rs0, 2);
        rs1 += __shfl_xor_sync(0xffffffffu, rs1, 1);
        rs1 += __shfl_xor_sync(0xffffffffu, rs1, 2);

        l0r = l0r * fac0 + rs0;
        l1r = l1r * fac1 + rs1;
        m0r = nm0; m1r = nm1;
        #pragma unroll
        for (int ni = 0; ni < 8; ni++) {
            o[ni][0] *= fac0; o[ni][1] *= fac0;
            o[ni][2] *= fac1; o[ni][3] *= fac1;
        }

        __syncwarp();   // P visible to all lanes of this warp

        // ---- O += P @ V : m16 x n64 x k128 ----
        #pragma unroll
        for (int kk = 0; kk < 16; kk++) {
            uint32_t afr[4];
            afr[0] = uP[(q0 + g) * 132 + kk * 8 + t];
            afr[1] = uP[(q0 + g + 8) * 132 + kk * 8 + t];
            afr[2] = uP[(q0 + g) * 132 + kk * 8 + t + 4];
            afr[3] = uP[(q0 + g + 8) * 132 + kk * 8 + t + 4];
            #pragma unroll
            for (int ni = 0; ni < 8; ni++) {
                uint32_t bfr[2];
                bfr[0] = uV[(kk * 8 + t) * 68 + ni * 8 + g];
                bfr[1] = uV[(kk * 8 + t + 4) * 68 + ni * 8 + g];
                MMA8(o[ni], afr, bfr);
            }
        }
    }

    // ---- normalize + write ----
    float inv0 = 1.0f / l0r, inv1 = 1.0f / l1r;
    float* aobase = ao + (size_t)(b * SEQ + qt * 128) * HDIM + h * HS;
    #pragma unroll
    for (int ni = 0; ni < 8; ni++) {
        int c = ni * 8 + 2 * t;
        *(float2*)(aobase + (size_t)(q0 + g) * HDIM + c) =
            make_float2(o[ni][0] * inv0, o[ni][1] * inv0);
        *(float2*)(aobase + (size_t)(q0 + g + 8) * HDIM + c) =
            make_float2(o[ni][2] * inv1, o[ni][3] * inv1);
    }
}

// ---------------------------------------------------------------------------
extern "C" void kernel_launch(void* const* d_in, const int* in_sizes, int n_in,
                              void* d_out, int out_size)
{
    const float* x    = (const float*)d_in[0];   // [2, 2048, 1024]
    const float* pos  = (const float*)d_in[1];   // [2048, 1024]
    const float* Wqkv = (const float*)d_in[2];   // [1024, 3072]
    const float* Wout = (const float*)d_in[3];   // [1024, 1024]
    float* out = (float*)d_out;                  // [2, 2048, 1024]

    float *qkv_p, *ao_p;
    cudaGetSymbolAddress((void**)&qkv_p, g_qkv);
    cudaGetSymbolAddress((void**)&ao_p,  g_ao);

    // 1) qkv = [(x+pos) @ Wqkv[:, :2H] | x @ Wqkv[:, 2H:]]
    {
        dim3 grid(N_QKV / 128, MTOT / 128);
        gemm_tf32<<<grid, 256>>>(x, pos, Wqkv, qkv_p, N_QKV, HDIM, 2 * HDIM);
    }

    // 2) flash attention (tf32 mma)
    {
        cudaFuncSetAttribute(attn_tf32,
                             cudaFuncAttributeMaxDynamicSharedMemorySize, ATTN_SMEM_BYTES);
        dim3 grid(SEQ / 128, 2 * NH);
        attn_tf32<<<grid, 256, ATTN_SMEM_BYTES>>>(qkv_p, ao_p);
    }

    // 3) out = ao @ Wout
    {
        dim3 grid(HDIM / 128, MTOT / 128);
        gemm_tf32<<<grid, 256>>>(ao_p, nullptr, Wout, out, HDIM, HDIM, 0);
    }
}

// round 3
// speedup vs baseline: 2.4438x; 1.0300x over previous
#include <cuda_runtime.h>
#include <math.h>
#include <stdint.h>

#define SEQ    2048
#define HDIM   1024
#define NH     16
#define HS     64
#define MTOT   4096            // B*S
#define N_QKV  3072            // 3*HDIM

// Scratch (allocation-free rule: device globals)
__device__ float g_qkv[(size_t)MTOT * N_QKV];   // [4096, 3072] : q | k | v
__device__ float g_ao [(size_t)MTOT * HDIM];    // attention output [4096, 1024]

// ---------------------------------------------------------------------------
// helpers
// ---------------------------------------------------------------------------
__device__ __forceinline__ uint32_t f2tf(float x) {
    uint32_t u;
    asm("cvt.rna.tf32.f32 %0, %1;" : "=r"(u) : "f"(x));
    return u;
}
__device__ __forceinline__ uint4 f2tf4(float4 a) {
    uint4 u;
    u.x = f2tf(a.x); u.y = f2tf(a.y); u.z = f2tf(a.z); u.w = f2tf(a.w);
    return u;
}
__device__ __forceinline__ float ex2(float x) {
    float r;
    asm("ex2.approx.ftz.f32 %0, %1;" : "=f"(r) : "f"(x));
    return r;
}

#define MMA8(d, a, b)                                                          \
    asm volatile(                                                              \
        "mma.sync.aligned.m16n8k8.row.col.f32.tf32.tf32.f32 "                  \
        "{%0,%1,%2,%3},{%4,%5,%6,%7},{%8,%9},{%0,%1,%2,%3};"                   \
        : "+f"((d)[0]), "+f"((d)[1]), "+f"((d)[2]), "+f"((d)[3])               \
        : "r"((a)[0]), "r"((a)[1]), "r"((a)[2]), "r"((a)[3]),                  \
          "r"((b)[0]), "r"((b)[1]))

// ---------------------------------------------------------------------------
// tf32 GEMM, software-pipelined: C[M,N] = A'[M,K] @ B[K,N];
// A' = A + pos for n-block < pos_ncut. 128x128x32 tile, 256 threads,
// warp tile 64x32. Double-buffered smem + global prefetch into registers.
// As row-major [128][36], Bs k-major [32][132] (both conflict-free).
// ---------------------------------------------------------------------------
__global__ __launch_bounds__(256, 2)
void gemm_tf32(const float* __restrict__ A,
               const float* __restrict__ pos,
               const float* __restrict__ B,
               float* __restrict__ C,
               int N, int K, int pos_ncut)
{
    __shared__ uint32_t As[2][128 * 36];
    __shared__ uint32_t Bs[2][32 * 132];

    const int tid  = threadIdx.x;
    const int lane = tid & 31;
    const int warp = tid >> 5;
    const int wm   = warp >> 2;          // 0..1
    const int wn   = warp & 3;           // 0..3
    const int g    = lane >> 2;          // 0..7
    const int t    = lane & 3;           // 0..3

    const int m0 = blockIdx.y * 128;
    const int n0 = blockIdx.x * 128;
    const bool addpos = (pos != nullptr) && (n0 < pos_ncut);

    float4 aS[4], bS[4];

    // global -> regs
    auto ldg = [&](int k0) {
        #pragma unroll
        for (int it = 0; it < 4; it++) {
            int f   = tid + it * 256;
            int row = f >> 3;
            int c4  = (f & 7) << 2;
            float4 a = *(const float4*)(A + (size_t)(m0 + row) * K + k0 + c4);
            if (addpos) {
                float4 p = *(const float4*)(pos + (size_t)((m0 + row) & (SEQ - 1)) * K + k0 + c4);
                a.x += p.x; a.y += p.y; a.z += p.z; a.w += p.w;
            }
            aS[it] = a;
        }
        #pragma unroll
        for (int it = 0; it < 4; it++) {
            int f  = tid + it * 256;
            int kr = f >> 5;
            int c4 = (f & 31) << 2;
            bS[it] = *(const float4*)(B + (size_t)(k0 + kr) * N + n0 + c4);
        }
    };
    // regs -> smem (tf32)
    auto sts = [&](int bf) {
        #pragma unroll
        for (int it = 0; it < 4; it++) {
            int f   = tid + it * 256;
            int row = f >> 3;
            int c4  = (f & 7) << 2;
            *(uint4*)&As[bf][row * 36 + c4] = f2tf4(aS[it]);
        }
        #pragma unroll
        for (int it = 0; it < 4; it++) {
            int f  = tid + it * 256;
            int kr = f >> 5;
            int c4 = (f & 31) << 2;
            *(uint4*)&Bs[bf][kr * 132 + c4] = f2tf4(bS[it]);
        }
    };

    float acc[4][4][4];
    #pragma unroll
    for (int i = 0; i < 4; i++)
        #pragma unroll
        for (int j = 0; j < 4; j++)
            #pragma unroll
            for (int c = 0; c < 4; c++)
                acc[i][j][c] = 0.0f;

    ldg(0);
    sts(0);
    __syncthreads();

    int buf = 0;
    for (int k0 = 0; k0 < K; k0 += 32) {
        const bool more = (k0 + 32 < K);
        if (more) ldg(k0 + 32);          // prefetch next tile (latency hidden by MMAs)

        #pragma unroll
        for (int ks = 0; ks < 4; ks++) {
            uint32_t afr[4][4], bfr[4][2];
            #pragma unroll
            for (int mi = 0; mi < 4; mi++) {
                int r = wm * 64 + mi * 16 + g;
                afr[mi][0] = As[buf][r * 36 + ks * 8 + t];
                afr[mi][1] = As[buf][(r + 8) * 36 + ks * 8 + t];
                afr[mi][2] = As[buf][r * 36 + ks * 8 + t + 4];
                afr[mi][3] = As[buf][(r + 8) * 36 + ks * 8 + t + 4];
            }
            #pragma unroll
            for (int ni = 0; ni < 4; ni++) {
                int n = wn * 32 + ni * 8 + g;
                bfr[ni][0] = Bs[buf][(ks * 8 + t) * 132 + n];
                bfr[ni][1] = Bs[buf][(ks * 8 + t + 4) * 132 + n];
            }
            #pragma unroll
            for (int mi = 0; mi < 4; mi++)
                #pragma unroll
                for (int ni = 0; ni < 4; ni++)
                    MMA8(acc[mi][ni], afr[mi], bfr[ni]);
        }

        if (more) {
            sts(buf ^ 1);                // other buffer: no barrier needed before
            __syncthreads();
            buf ^= 1;
        }
    }

    #pragma unroll
    for (int mi = 0; mi < 4; mi++) {
        int row = m0 + wm * 64 + mi * 16 + g;
        #pragma unroll
        for (int ni = 0; ni < 4; ni++) {
            int col = n0 + wn * 32 + ni * 8 + 2 * t;
            *(float2*)(C + (size_t)row * N + col)       = make_float2(acc[mi][ni][0], acc[mi][ni][1]);
            *(float2*)(C + (size_t)(row + 8) * N + col) = make_float2(acc[mi][ni][2], acc[mi][ni][3]);
        }
    }
}

// ---------------------------------------------------------------------------
// Flash attention (causal), tf32 mma + fp32 softmax.
// CTA = (b, h, 128 q-rows), 256 threads, warp owns 16 q-rows.
// P never touches smem: PV A-fragments built from score registers via
// intra-quad shuffles. smem = uQ[128][68] + uK[64][132] + uV[128][68]
// = 101 KB -> 2 CTAs/SM.
// ---------------------------------------------------------------------------
#define ATTN_SMEM_BYTES ((128*68 + 64*132 + 128*68) * 4)

__global__ __launch_bounds__(256, 2)
void attn_tf32(const float* __restrict__ qkv, float* __restrict__ ao)
{
    extern __shared__ uint32_t usm[];
    uint32_t* uQ = usm;                  // 128*68
    uint32_t* uK = uQ + 128 * 68;        // 64*132
    uint32_t* uV = uK + 64 * 132;        // 128*68

    const int tid  = threadIdx.x;
    const int lane = tid & 31;
    const int warp = tid >> 5;
    const int g    = lane >> 2;          // 0..7
    const int t    = lane & 3;           // 0..3
    const int q0   = warp * 16;
    const unsigned FULL = 0xffffffffu;

    const int bh = blockIdx.y;
    const int b  = bh >> 4;
    const int h  = bh & 15;
    const int qt = (int)gridDim.x - 1 - (int)blockIdx.x;   // heavy tiles first

    const size_t rs = N_QKV;
    const float* qbase = qkv + (size_t)(b * SEQ + qt * 128) * rs + h * HS;

    // ---- stage Q (scaled by exact 0.125), row-major ----
    #pragma unroll
    for (int it = 0; it < 8; it++) {
        int f   = tid + it * 256;
        int row = f >> 4;
        int c4  = (f & 15) << 2;
        float4 v = *(const float4*)(qbase + (size_t)row * rs + c4);
        v.x *= 0.125f; v.y *= 0.125f; v.z *= 0.125f; v.w *= 0.125f;
        *(uint4*)&uQ[row * 68 + c4] = f2tf4(v);
    }

    float m0r = -1e30f, m1r = -1e30f, l0r = 0.0f, l1r = 0.0f;
    float o[8][4];
    #pragma unroll
    for (int ni = 0; ni < 8; ni++)
        o[ni][0] = o[ni][1] = o[ni][2] = o[ni][3] = 0.0f;

    const float L2E = 1.4426950408889634f;

    for (int kt = 0; kt <= qt; kt++) {
        __syncthreads();   // Q staged (iter 0) / prev PV reads of uV done

        const float* kbase = qkv + (size_t)(b * SEQ + kt * 128) * rs + HDIM + h * HS;
        const float* vbase = kbase + HDIM;

        // K: store transposed uK[d][key]
        #pragma unroll
        for (int it = 0; it < 8; it++) {
            int key = (lane >> 2) + 8 * ((it & 1) + 2 * warp);
            int c4  = (lane & 3) * 4 + (it >> 1) * 16;
            float4 kv = *(const float4*)(kbase + (size_t)key * rs + c4);
            uK[(c4 + 0) * 132 + key] = f2tf(kv.x);
            uK[(c4 + 1) * 132 + key] = f2tf(kv.y);
            uK[(c4 + 2) * 132 + key] = f2tf(kv.z);
            uK[(c4 + 3) * 132 + key] = f2tf(kv.w);
        }
        // V: row-major
        #pragma unroll
        for (int it = 0; it < 8; it++) {
            int f   = tid + it * 256;
            int row = f >> 4;
            int c4  = (f & 15) << 2;
            float4 vv = *(const float4*)(vbase + (size_t)row * rs + c4);
            *(uint4*)&uV[row * 68 + c4] = f2tf4(vv);
        }
        __syncthreads();

        // ---- S = Q @ K^T : per warp m16 x n128 x k64 ----
        float sacc[16][4];
        #pragma unroll
        for (int ni = 0; ni < 16; ni++)
            sacc[ni][0] = sacc[ni][1] = sacc[ni][2] = sacc[ni][3] = 0.0f;

        #pragma unroll
        for (int ks = 0; ks < 8; ks++) {
            uint32_t afr[4];
            afr[0] = uQ[(q0 + g) * 68 + ks * 8 + t];
            afr[1] = uQ[(q0 + g + 8) * 68 + ks * 8 + t];
            afr[2] = uQ[(q0 + g) * 68 + ks * 8 + t + 4];
            afr[3] = uQ[(q0 + g + 8) * 68 + ks * 8 + t + 4];
            #pragma unroll
            for (int ni = 0; ni < 16; ni++) {
                uint32_t bfr[2];
                bfr[0] = uK[(ks * 8 + t) * 132 + ni * 8 + g];
                bfr[1] = uK[(ks * 8 + t + 4) * 132 + ni * 8 + g];
                MMA8(sacc[ni], afr, bfr);
            }
        }

        // ---- causal mask (diagonal tile only) ----
        const int r0l = q0 + g, r1l = r0l + 8;
        if (kt == qt) {
            #pragma unroll
            for (int ni = 0; ni < 16; ni++) {
                int c = ni * 8 + 2 * t;
                if (c     > r0l) sacc[ni][0] = -1e30f;
                if (c + 1 > r0l) sacc[ni][1] = -1e30f;
                if (c     > r1l) sacc[ni][2] = -1e30f;
                if (c + 1 > r1l) sacc[ni][3] = -1e30f;
            }
        }

        // ---- row max (quad reduce) ----
        float rm0 = -1e30f, rm1 = -1e30f;
        #pragma unroll
        for (int ni = 0; ni < 16; ni++) {
            rm0 = fmaxf(rm0, fmaxf(sacc[ni][0], sacc[ni][1]));
            rm1 = fmaxf(rm1, fmaxf(sacc[ni][2], sacc[ni][3]));
        }
        rm0 = fmaxf(rm0, __shfl_xor_sync(FULL, rm0, 1));
        rm0 = fmaxf(rm0, __shfl_xor_sync(FULL, rm0, 2));
        rm1 = fmaxf(rm1, __shfl_xor_sync(FULL, rm1, 1));
        rm1 = fmaxf(rm1, __shfl_xor_sync(FULL, rm1, 2));

        float nm0 = fmaxf(m0r, rm0), nm1 = fmaxf(m1r, rm1);
        float fac0 = ex2((m0r - nm0) * L2E), fac1 = ex2((m1r - nm1) * L2E);
        float nb0 = nm0 * L2E, nb1 = nm1 * L2E;   // base-2 biases

        // ---- exp in place + row sums ----
        float rs0 = 0.0f, rs1 = 0.0f;
        #pragma unroll
        for (int ni = 0; ni < 16; ni++) {
            float p00 = ex2(fmaf(sacc[ni][0], L2E, -nb0));
            float p01 = ex2(fmaf(sacc[ni][1], L2E, -nb0));
            float p10 = ex2(fmaf(sacc[ni][2], L2E, -nb1));
            float p11 = ex2(fmaf(sacc[ni][3], L2E, -nb1));
            sacc[ni][0] = p00; sacc[ni][1] = p01;
            sacc[ni][2] = p10; sacc[ni][3] = p11;
            rs0 += p00 + p01;
            rs1 += p10 + p11;
        }
        rs0 += __shfl_xor_sync(FULL, rs0, 1);
        rs0 += __shfl_xor_sync(FULL, rs0, 2);
        rs1 += __shfl_xor_sync(FULL, rs1, 1);
        rs1 += __shfl_xor_sync(FULL, rs1, 2);

        l0r = l0r * fac0 + rs0;
        l1r = l1r * fac1 + rs1;
        m0r = nm0; m1r = nm1;
        #pragma unroll
        for (int ni = 0; ni < 8; ni++) {
            o[ni][0] *= fac0; o[ni][1] *= fac0;
            o[ni][2] *= fac1; o[ni][3] *= fac1;
        }

        // ---- O += P @ V : A-frags built via intra-quad shuffles ----
        const int sA = (lane & ~3) | (t >> 1);   // src lane for col t
        const int sB = sA + 2;                   // src lane for col t+4
        const bool odd = (t & 1);
        #pragma unroll
        for (int kk = 0; kk < 16; kk++) {
            float e0 = sacc[kk][0], e1 = sacc[kk][1];
            float e2 = sacc[kk][2], e3 = sacc[kk][3];
            float r0e = __shfl_sync(FULL, e0, sA);
            float r0o = __shfl_sync(FULL, e1, sA);
            float r4e = __shfl_sync(FULL, e0, sB);
            float r4o = __shfl_sync(FULL, e1, sB);
            float s0e = __shfl_sync(FULL, e2, sA);
            float s0o = __shfl_sync(FULL, e3, sA);
            float s4e = __shfl_sync(FULL, e2, sB);
            float s4o = __shfl_sync(FULL, e3, sB);
            uint32_t afr[4];
            afr[0] = f2tf(odd ? r0o : r0e);   // P[g][kk*8+t]
            afr[1] = f2tf(odd ? s0o : s0e);   // P[g+8][kk*8+t]
            afr[2] = f2tf(odd ? r4o : r4e);   // P[g][kk*8+t+4]
            afr[3] = f2tf(odd ? s4o : s4e);   // P[g+8][kk*8+t+4]
            #pragma unroll
            for (int ni = 0; ni < 8; ni++) {
                uint32_t bfr[2];
                bfr[0] = uV[(kk * 8 + t) * 68 + ni * 8 + g];
                bfr[1] = uV[(kk * 8 + t + 4) * 68 + ni * 8 + g];
                MMA8(o[ni], afr, bfr);
            }
        }
    }

    // ---- normalize + write ----
    float inv0 = 1.0f / l0r, inv1 = 1.0f / l1r;
    float* aobase = ao + (size_t)(b * SEQ + qt * 128) * HDIM + h * HS;
    #pragma unroll
    for (int ni = 0; ni < 8; ni++) {
        int c = ni * 8 + 2 * t;
        *(float2*)(aobase + (size_t)(q0 + g) * HDIM + c) =
            make_float2(o[ni][0] * inv0, o[ni][1] * inv0);
        *(float2*)(aobase + (size_t)(q0 + g + 8) * HDIM + c) =
            make_float2(o[ni][2] * inv1, o[ni][3] * inv1);
    }
}

// ---------------------------------------------------------------------------
extern "C" void kernel_launch(void* const* d_in, const int* in_sizes, int n_in,
                              void* d_out, int out_size)
{
    const float* x    = (const float*)d_in[0];   // [2, 2048, 1024]
    const float* pos  = (const float*)d_in[1];   // [2048, 1024]
    const float* Wqkv = (const float*)d_in[2];   // [1024, 3072]
    const float* Wout = (const float*)d_in[3];   // [1024, 1024]
    float* out = (float*)d_out;                  // [2, 2048, 1024]

    float *qkv_p, *ao_p;
    cudaGetSymbolAddress((void**)&qkv_p, g_qkv);
    cudaGetSymbolAddress((void**)&ao_p,  g_ao);

    // 1) qkv = [(x+pos) @ Wqkv[:, :2H] | x @ Wqkv[:, 2H:]]
    {
        dim3 grid(N_QKV / 128, MTOT / 128);
        gemm_tf32<<<grid, 256>>>(x, pos, Wqkv, qkv_p, N_QKV, HDIM, 2 * HDIM);
    }

    // 2) flash attention (tf32 mma, shuffle-P, 2 CTAs/SM)
    {
        cudaFuncSetAttribute(attn_tf32,
                             cudaFuncAttributeMaxDynamicSharedMemorySize, ATTN_SMEM_BYTES);
        dim3 grid(SEQ / 128, 2 * NH);
        attn_tf32<<<grid, 256, ATTN_SMEM_BYTES>>>(qkv_p, ao_p);
    }

    // 3) out = ao @ Wout
    {
        dim3 grid(HDIM / 128, MTOT / 128);
        gemm_tf32<<<grid, 256>>>(ao_p, nullptr, Wout, out, HDIM, HDIM, 0);
    }
}

// round 5
// speedup vs baseline: 4.4179x; 1.8078x over previous
#include <cuda_runtime.h>
#include <cuda_fp16.h>
#include <math.h>
#include <stdint.h>

#define SEQ    2048
#define HDIM   1024
#define NH     16
#define HS     64
#define MTOT   4096            // B*S
#define N_QKV  3072            // 3*HDIM

// Scratch (allocation-free rule: device globals)
__device__ float    g_ao   [(size_t)MTOT * HDIM];       // attention output (fp32)
__device__ __half   g_qkh  [(size_t)MTOT * 2048];       // q|k in half, row-major
__device__ __half   g_vT   [(size_t)HDIM * MTOT];       // v transposed [1024][4096]
__device__ uint32_t g_wqkvT2[(size_t)N_QKV * (HDIM / 2)]; // W_qkv^T, half2-packed k-pairs
__device__ uint32_t g_woutT2[(size_t)HDIM * (HDIM / 2)];  // W_out^T, half2-packed k-pairs

// ---------------------------------------------------------------------------
// helpers
// ---------------------------------------------------------------------------
__device__ __forceinline__ uint32_t f22h2(float x, float y) {
    __half2 h = __floats2half2_rn(x, y);
    return *(uint32_t*)&h;
}
__device__ __forceinline__ float ex2(float x) {
    float r;
    asm("ex2.approx.ftz.f32 %0, %1;" : "=f"(r) : "f"(x));
    return r;
}

#define MMA16(d, a, b)                                                         \
    asm volatile(                                                              \
        "mma.sync.aligned.m16n8k16.row.col.f32.f16.f16.f32 "                   \
        "{%0,%1,%2,%3},{%4,%5,%6,%7},{%8,%9},{%0,%1,%2,%3};"                   \
        : "+f"((d)[0]), "+f"((d)[1]), "+f"((d)[2]), "+f"((d)[3])               \
        : "r"((a)[0]), "r"((a)[1]), "r"((a)[2]), "r"((a)[3]),                  \
          "r"((b)[0]), "r"((b)[1]))

// ---------------------------------------------------------------------------
// Weight transpose + pack: W[K][N] fp32 -> WT2[n][k/2] half2
// ---------------------------------------------------------------------------
__global__ __launch_bounds__(256)
void transpose_h2(const float* __restrict__ W, uint32_t* __restrict__ WT2,
                  int K, int N)
{
    __shared__ float tile[32][33];
    const int bx = blockIdx.x;   // n tile
    const int by = blockIdx.y;   // k tile
    const int tx = threadIdx.x;
    const int ty = threadIdx.y;
    #pragma unroll
    for (int i = ty; i < 32; i += 8)
        tile[i][tx] = W[(size_t)(by * 32 + i) * N + bx * 32 + tx];
    __syncthreads();
    const int idx = ty * 32 + tx;
    #pragma unroll
    for (int it = 0; it < 2; it++) {
        int id = idx + it * 256;          // 0..511
        int nl = id >> 4;                 // 0..31
        int kh = id & 15;                 // 0..15
        WT2[(size_t)(bx * 32 + nl) * (K / 2) + by * 16 + kh] =
            f22h2(tile[2 * kh][nl], tile[2 * kh + 1][nl]);
    }
}

// ---------------------------------------------------------------------------
// fp16 GEMM: C = A'[M,K] @ W[K,N]; A fp32 (+pos for n<pos_ncut), W as WT2.
// 128x128x32 tile, 256 thr, warp tile 64x32. Double-buffered, reg prefetch.
// Ah[128][20] half2-words (pad 4);  Bh[n][16] XOR-swizzled (idx ^ 2*(n&7)).
// outmode 0: fp32 C.  outmode 1: n<2048 -> g_qkh half; n>=2048 -> g_vT half.
// ---------------------------------------------------------------------------
__global__ __launch_bounds__(256, 2)
void gemm_h16(const float* __restrict__ A, const float* __restrict__ pos,
              const uint32_t* __restrict__ BT2, float* __restrict__ Cf,
              __half* __restrict__ qkh, __half* __restrict__ vT,
              int N, int K, int pos_ncut, int outmode)
{
    __shared__ uint32_t Ah[2][128 * 20];
    __shared__ uint32_t Bh[2][128 * 16];

    const int tid  = threadIdx.x;
    const int lane = tid & 31;
    const int warp = tid >> 5;
    const int wm   = warp >> 2;
    const int wn   = warp & 3;
    const int g    = lane >> 2;
    const int t    = lane & 3;

    const int m0 = blockIdx.y * 128;
    const int n0 = blockIdx.x * 128;
    const bool addpos = (pos != nullptr) && (n0 < pos_ncut);

    float4 aS[4];
    uint4  bS[2];

    auto ldg = [&](int k0) {
        #pragma unroll
        for (int it = 0; it < 2; it++) {
            int f   = tid + it * 256;     // 0..511
            int row = f >> 2;
            int ch  = f & 3;              // 8-float chunk
            const float* ap = A + (size_t)(m0 + row) * K + k0 + ch * 8;
            float4 a0 = *(const float4*)ap;
            float4 a1 = *(const float4*)(ap + 4);
            if (addpos) {
                const float* pp = pos + (size_t)((m0 + row) & (SEQ - 1)) * K + k0 + ch * 8;
                float4 p0 = *(const float4*)pp;
                float4 p1 = *(const float4*)(pp + 4);
                a0.x += p0.x; a0.y += p0.y; a0.z += p0.z; a0.w += p0.w;
                a1.x += p1.x; a1.y += p1.y; a1.z += p1.z; a1.w += p1.w;
            }
            aS[2 * it] = a0; aS[2 * it + 1] = a1;
        }
        #pragma unroll
        for (int it = 0; it < 2; it++) {
            int f  = tid + it * 256;
            int n  = f >> 2;
            int c4 = f & 3;
            bS[it] = *(const uint4*)(BT2 + (size_t)(n0 + n) * (K / 2) + (k0 >> 1) + c4 * 4);
        }
    };
    auto sts = [&](int bf) {
        #pragma unroll
        for (int it = 0; it < 2; it++) {
            int f   = tid + it * 256;
            int row = f >> 2;
            int ch  = f & 3;
            float4 a0 = aS[2 * it], a1 = aS[2 * it + 1];
            uint4 u;
            u.x = f22h2(a0.x, a0.y); u.y = f22h2(a0.z, a0.w);
            u.z = f22h2(a1.x, a1.y); u.w = f22h2(a1.z, a1.w);
            *(uint4*)&Ah[bf][row * 20 + ch * 4] = u;
        }
        #pragma unroll
        for (int it = 0; it < 2; it++) {
            int f  = tid + it * 256;
            int n  = f >> 2;
            int c4 = f & 3;
            uint4 u = bS[it];
            int sw = 2 * (n & 7);
            int iA = (4 * c4) ^ sw;
            int iB = (4 * c4 + 2) ^ sw;
            *(uint2*)&Bh[bf][n * 16 + iA] = make_uint2(u.x, u.y);
            *(uint2*)&Bh[bf][n * 16 + iB] = make_uint2(u.z, u.w);
        }
    };

    float acc[4][4][4];
    #pragma unroll
    for (int i = 0; i < 4; i++)
        #pragma unroll
        for (int j = 0; j < 4; j++)
            #pragma unroll
            for (int c = 0; c < 4; c++)
                acc[i][j][c] = 0.0f;

    ldg(0);
    sts(0);
    __syncthreads();

    int buf = 0;
    for (int k0 = 0; k0 < K; k0 += 32) {
        const bool more = (k0 + 32 < K);
        if (more) ldg(k0 + 32);

        #pragma unroll
        for (int ks = 0; ks < 2; ks++) {
            uint32_t afr[4][4], bfr[4][2];
            #pragma unroll
            for (int mi = 0; mi < 4; mi++) {
                int r = wm * 64 + mi * 16 + g;
                afr[mi][0] = Ah[buf][r * 20 + ks * 8 + t];
                afr[mi][1] = Ah[buf][(r + 8) * 20 + ks * 8 + t];
                afr[mi][2] = Ah[buf][r * 20 + ks * 8 + t + 4];
                afr[mi][3] = Ah[buf][(r + 8) * 20 + ks * 8 + t + 4];
            }
            #pragma unroll
            for (int ni = 0; ni < 4; ni++) {
                int n  = wn * 32 + ni * 8 + g;
                int sw = 2 * (n & 7);
                bfr[ni][0] = Bh[buf][n * 16 + ((ks * 8 + t) ^ sw)];
                bfr[ni][1] = Bh[buf][n * 16 + ((ks * 8 + t + 4) ^ sw)];
            }
            #pragma unroll
            for (int mi = 0; mi < 4; mi++)
                #pragma unroll
                for (int ni = 0; ni < 4; ni++)
                    MMA16(acc[mi][ni], afr[mi], bfr[ni]);
        }

        if (more) {
            sts(buf ^ 1);
            __syncthreads();
            buf ^= 1;
        }
    }

    // ---- epilogue ----
    if (outmode == 0) {
        #pragma unroll
        for (int mi = 0; mi < 4; mi++) {
            int row = m0 + wm * 64 + mi * 16 + g;
            #pragma unroll
            for (int ni = 0; ni < 4; ni++) {
                int col = n0 + wn * 32 + ni * 8 + 2 * t;
                *(float2*)(Cf + (size_t)row * N + col) =
                    make_float2(acc[mi][ni][0], acc[mi][ni][1]);
                *(float2*)(Cf + (size_t)(row + 8) * N + col) =
                    make_float2(acc[mi][ni][2], acc[mi][ni][3]);
            }
        }
    } else if (n0 < 2048) {
        #pragma unroll
        for (int mi = 0; mi < 4; mi++) {
            int row = m0 + wm * 64 + mi * 16 + g;
            #pragma unroll
            for (int ni = 0; ni < 4; ni++) {
                int col = n0 + wn * 32 + ni * 8 + 2 * t;
                *(uint32_t*)(qkh + (size_t)row * 2048 + col) =
                    f22h2(acc[mi][ni][0], acc[mi][ni][1]);
                *(uint32_t*)(qkh + (size_t)(row + 8) * 2048 + col) =
                    f22h2(acc[mi][ni][2], acc[mi][ni][3]);
            }
        }
    } else {
        #pragma unroll
        for (int mi = 0; mi < 4; mi++) {
            int row = m0 + wm * 64 + mi * 16 + g;
            #pragma unroll
            for (int ni = 0; ni < 4; ni++) {
                int colv = n0 - 2048 + wn * 32 + ni * 8 + 2 * t;
                vT[(size_t)colv * MTOT + row]           = __float2half_rn(acc[mi][ni][0]);
                vT[(size_t)(colv + 1) * MTOT + row]     = __float2half_rn(acc[mi][ni][1]);
                vT[(size_t)colv * MTOT + row + 8]       = __float2half_rn(acc[mi][ni][2]);
                vT[(size_t)(colv + 1) * MTOT + row + 8] = __float2half_rn(acc[mi][ni][3]);
            }
        }
    }
}

// ---------------------------------------------------------------------------
// Flash attention (causal), fp16 mma m16n8k16 + fp32 softmax.
// CTA = (b, h, 128 q-rows), 256 thr, warp owns 16 rows. Q frags in regs,
// P entirely in regs (QK C-layout == PV A-layout). K/V double-buffered smem,
// one __syncthreads per k-tile, staging overlapped with PV.
// smem: per buffer: Kh 128x128B (SW128) + vPh 64x64 words (XOR (d&7)<<2).
// ---------------------------------------------------------------------------
#define ATTN_SMEM_BYTES (4 * 4096 * 4)   // 2 buffers x (4096 + 4096) words

__global__ __launch_bounds__(256, 2)
void attn_h16(const __half* __restrict__ qkh, const __half* __restrict__ vT,
              float* __restrict__ ao)
{
    extern __shared__ uint32_t usm[];
    // buffer layout: [buf*8192 + 0 .. 4095] = K, [buf*8192 + 4096 ..] = V

    const int tid  = threadIdx.x;
    const int lane = tid & 31;
    const int warp = tid >> 5;
    const int g    = lane >> 2;
    const int t    = lane & 3;
    const int q0   = warp * 16;
    const int g4   = g << 2;
    const unsigned FULL = 0xffffffffu;

    const int bh = blockIdx.y;
    const int b  = bh >> 4;
    const int h  = bh & 15;
    const int qt = (int)gridDim.x - 1 - (int)blockIdx.x;

    // ---- Q fragments in registers (scaled by exact 0.125) ----
    uint32_t qf[4][4];
    {
        const __half* qb = qkh + (size_t)(b * SEQ + qt * 128 + q0 + g) * 2048 + h * HS;
        const __half2 s = __floats2half2_rn(0.125f, 0.125f);
        #pragma unroll
        for (int ks = 0; ks < 4; ks++) {
            __half2 v0 = *(const __half2*)(qb + ks * 16 + 2 * t);
            __half2 v1 = *(const __half2*)(qb + 8 * 2048 + ks * 16 + 2 * t);
            __half2 v2 = *(const __half2*)(qb + ks * 16 + 2 * t + 8);
            __half2 v3 = *(const __half2*)(qb + 8 * 2048 + ks * 16 + 2 * t + 8);
            v0 = __hmul2(v0, s); v1 = __hmul2(v1, s);
            v2 = __hmul2(v2, s); v3 = __hmul2(v3, s);
            qf[ks][0] = *(uint32_t*)&v0; qf[ks][1] = *(uint32_t*)&v1;
            qf[ks][2] = *(uint32_t*)&v2; qf[ks][3] = *(uint32_t*)&v3;
        }
    }

    const __half* kb0 = qkh + (size_t)(b * SEQ) * 2048 + 1024 + h * HS;
    const __half* vb0 = vT + (size_t)(h * HS) * MTOT + b * SEQ;

    auto stageK = [&](int kt2, uint32_t* Kbuf) {
        const __half* kb = kb0 + (size_t)(kt2 * 128) * 2048;
        #pragma unroll
        for (int it = 0; it < 4; it++) {
            int id  = tid + it * 256;
            int key = id >> 3;
            int ch  = id & 7;
            uint4 u = *(const uint4*)(kb + (size_t)key * 2048 + ch * 8);
            uint32_t off = ((uint32_t)key << 5) + (ch << 2);      // word offset
            off ^= (uint32_t)(key & 7) << 2;                       // SW128 (words)
            *(uint4*)(Kbuf + off) = u;
        }
    };
    auto stageV = [&](int kt2, uint32_t* Vbuf) {
        const __half* vb = vb0 + kt2 * 128;
        #pragma unroll
        for (int it = 0; it < 4; it++) {
            int id = tid + it * 256;
            int d  = id >> 4;
            int ch = id & 15;
            uint4 u = *(const uint4*)(vb + (size_t)d * MTOT + ch * 8);
            uint32_t widx = (uint32_t)(ch * 4) ^ ((uint32_t)(d & 7) << 2);
            *(uint4*)(Vbuf + d * 64 + widx) = u;
        }
    };

    float m0r = -1e30f, m1r = -1e30f, l0r = 0.0f, l1r = 0.0f;
    float o[8][4];
    #pragma unroll
    for (int ni = 0; ni < 8; ni++)
        o[ni][0] = o[ni][1] = o[ni][2] = o[ni][3] = 0.0f;

    const float L2E = 1.4426950408889634f;

    stageK(0, usm);
    stageV(0, usm + 4096);
    __syncthreads();

    int buf = 0;
    for (int kt = 0; kt <= qt; kt++) {
        const uint32_t* Kbuf = usm + buf * 8192;
        const uint32_t* Vbuf = Kbuf + 4096;

        // ---- S = Q @ K^T : m16 x n128 x k64 ----
        float sacc[16][4];
        #pragma unroll
        for (int ni = 0; ni < 16; ni++)
            sacc[ni][0] = sacc[ni][1] = sacc[ni][2] = sacc[ni][3] = 0.0f;

        #pragma unroll
        for (int ks = 0; ks < 4; ks++) {
            const int i0 = ks * 8 + t;
            const int w0 = i0 ^ g4;
            const int w1 = (i0 + 4) ^ g4;
            #pragma unroll
            for (int ni = 0; ni < 16; ni++) {
                const uint32_t* kr = Kbuf + (ni * 8 + g) * 32;
                uint32_t bfr[2] = { kr[w0], kr[w1] };
                MMA16(sacc[ni], qf[ks], bfr);
            }
        }

        // ---- causal mask (diagonal tile only) ----
        const int r0l = q0 + g, r1l = r0l + 8;
        if (kt == qt) {
            #pragma unroll
            for (int ni = 0; ni < 16; ni++) {
                int c = ni * 8 + 2 * t;
                if (c     > r0l) sacc[ni][0] = -1e30f;
                if (c + 1 > r0l) sacc[ni][1] = -1e30f;
                if (c     > r1l) sacc[ni][2] = -1e30f;
                if (c + 1 > r1l) sacc[ni][3] = -1e30f;
            }
        }

        // ---- row max (quad reduce) ----
        float rm0 = -1e30f, rm1 = -1e30f;
        #pragma unroll
        for (int ni = 0; ni < 16; ni++) {
            rm0 = fmaxf(rm0, fmaxf(sacc[ni][0], sacc[ni][1]));
            rm1 = fmaxf(rm1, fmaxf(sacc[ni][2], sacc[ni][3]));
        }
        rm0 = fmaxf(rm0, __shfl_xor_sync(FULL, rm0, 1));
        rm0 = fmaxf(rm0, __shfl_xor_sync(FULL, rm0, 2));
        rm1 = fmaxf(rm1, __shfl_xor_sync(FULL, rm1, 1));
        rm1 = fmaxf(rm1, __shfl_xor_sync(FULL, rm1, 2));

        float nm0 = fmaxf(m0r, rm0), nm1 = fmaxf(m1r, rm1);
        float fac0 = ex2((m0r - nm0) * L2E), fac1 = ex2((m1r - nm1) * L2E);
        float nb0 = nm0 * L2E, nb1 = nm1 * L2E;

        // ---- exp + row sums + pack P to half2 (QK C-layout == PV A-layout) ----
        uint32_t p01[16], p23[16];
        float rs0 = 0.0f, rs1 = 0.0f;
        #pragma unroll
        for (int ni = 0; ni < 16; ni++) {
            float p00 = ex2(fmaf(sacc[ni][0], L2E, -nb0));
            float p01v = ex2(fmaf(sacc[ni][1], L2E, -nb0));
            float p10 = ex2(fmaf(sacc[ni][2], L2E, -nb1));
            float p11 = ex2(fmaf(sacc[ni][3], L2E, -nb1));
            rs0 += p00 + p01v;
            rs1 += p10 + p11;
            p01[ni] = f22h2(p00, p01v);
            p23[ni] = f22h2(p10, p11);
        }
        rs0 += __shfl_xor_sync(FULL, rs0, 1);
        rs0 += __shfl_xor_sync(FULL, rs0, 2);
        rs1 += __shfl_xor_sync(FULL, rs1, 1);
        rs1 += __shfl_xor_sync(FULL, rs1, 2);

        l0r = l0r * fac0 + rs0;
        l1r = l1r * fac1 + rs1;
        m0r = nm0; m1r = nm1;
        #pragma unroll
        for (int ni = 0; ni < 8; ni++) {
            o[ni][0] *= fac0; o[ni][1] *= fac0;
            o[ni][2] *= fac1; o[ni][3] *= fac1;
        }

        // ---- stage next K/V tile into other buffer (overlaps with PV) ----
        if (kt < qt) {
            uint32_t* nb = usm + (buf ^ 1) * 8192;
            stageK(kt + 1, nb);
            stageV(kt + 1, nb + 4096);
        }

        // ---- O += P @ V : m16 x n64 x k128 ----
        #pragma unroll
        for (int kk = 0; kk < 8; kk++) {
            uint32_t afr[4] = { p01[2 * kk], p23[2 * kk],
                                p01[2 * kk + 1], p23[2 * kk + 1] };
            const int i0 = kk * 8 + t;
            #pragma unroll
            for (int ni = 0; ni < 8; ni++) {
                const int d = ni * 8 + g;
                const uint32_t* vr = Vbuf + d * 64;
                uint32_t bfr[2] = { vr[i0 ^ g4], vr[(i0 + 4) ^ g4] };
                MMA16(o[ni], afr, bfr);
            }
        }

        if (kt < qt) {
            __syncthreads();
            buf ^= 1;
        }
    }

    // ---- normalize + write fp32 ao ----
    float inv0 = 1.0f / l0r, inv1 = 1.0f / l1r;
    float* aobase = ao + (size_t)(b * SEQ + qt * 128) * HDIM + h * HS;
    #pragma unroll
    for (int ni = 0; ni < 8; ni++) {
        int c = ni * 8 + 2 * t;
        *(float2*)(aobase + (size_t)(q0 + g) * HDIM + c) =
            make_float2(o[ni][0] * inv0, o[ni][1] * inv0);
        *(float2*)(aobase + (size_t)(q0 + g + 8) * HDIM + c) =
            make_float2(o[ni][2] * inv1, o[ni][3] * inv1);
    }
}

// ---------------------------------------------------------------------------
extern "C" void kernel_launch(void* const* d_in, const int* in_sizes, int n_in,
                              void* d_out, int out_size)
{
    const float* x    = (const float*)d_in[0];   // [2, 2048, 1024]
    const float* pos  = (const float*)d_in[1];   // [2048, 1024]
    const float* Wqkv = (const float*)d_in[2];   // [1024, 3072]
    const float* Wout = (const float*)d_in[3];   // [1024, 1024]
    float* out = (float*)d_out;                  // [2, 2048, 1024]

    float*    ao_p;
    __half *qkh_p, *vT_p;
    uint32_t *wqkvT2_p, *woutT2_p;
    cudaGetSymbolAddress((void**)&ao_p,     g_ao);
    cudaGetSymbolAddress((void**)&qkh_p,    g_qkh);
    cudaGetSymbolAddress((void**)&vT_p,     g_vT);
    cudaGetSymbolAddress((void**)&wqkvT2_p, g_wqkvT2);
    cudaGetSymbolAddress((void**)&woutT2_p, g_woutT2);

    // 0) transpose + half2-pack weights
    transpose_h2<<<dim3(N_QKV / 32, HDIM / 32), dim3(32, 8)>>>(Wqkv, wqkvT2_p, HDIM, N_QKV);
    transpose_h2<<<dim3(HDIM / 32, HDIM / 32), dim3(32, 8)>>>(Wout, woutT2_p, HDIM, HDIM);

    // 1) qkv projection -> half outputs (q|k row-major, v transposed)
    {
        dim3 grid(N_QKV / 128, MTOT / 128);
        gemm_h16<<<grid, 256>>>(x, pos, wqkvT2_p, nullptr, qkh_p, vT_p,
                                N_QKV, HDIM, 2 * HDIM, 1);
    }

    // 2) flash attention (fp16 mma, P in regs, double-buffered K/V)
    {
        cudaFuncSetAttribute(attn_h16,
                             cudaFuncAttributeMaxDynamicSharedMemorySize, ATTN_SMEM_BYTES);
        dim3 grid(SEQ / 128, 2 * NH);
        attn_h16<<<grid, 256, ATTN_SMEM_BYTES>>>(qkh_p, vT_p, ao_p);
    }

    // 3) out = ao @ Wout (fp32 output)
    {
        dim3 grid(HDIM / 128, MTOT / 128);
        gemm_h16<<<grid, 256>>>(ao_p, nullptr, woutT2_p, out, nullptr, nullptr,
                                HDIM, HDIM, 0, 0);
    }
}

// round 6
// speedup vs baseline: 4.8847x; 1.1057x over previous
#include <cuda_runtime.h>
#include <cuda_fp16.h>
#include <math.h>
#include <stdint.h>

#define SEQ    2048
#define HDIM   1024
#define NH     16
#define HS     64
#define MTOT   4096            // B*S
#define N_QKV  3072            // 3*HDIM

// Scratch (allocation-free rule: device globals)
__device__ float    g_ao   [(size_t)MTOT * HDIM];       // attention output (fp32)
__device__ __half   g_qkh  [(size_t)MTOT * 2048];       // q|k in half, row-major
__device__ __half   g_vT   [(size_t)HDIM * MTOT];       // v transposed [1024][4096]
__device__ uint32_t g_wqkvT2[(size_t)N_QKV * (HDIM / 2)]; // W_qkv^T, half2-packed
__device__ uint32_t g_woutT2[(size_t)HDIM * (HDIM / 2)];  // W_out^T, half2-packed

// ---------------------------------------------------------------------------
// helpers
// ---------------------------------------------------------------------------
__device__ __forceinline__ uint32_t f22h2(float x, float y) {
    __half2 h = __floats2half2_rn(x, y);
    return *(uint32_t*)&h;
}
__device__ __forceinline__ float ex2(float x) {
    float r;
    asm("ex2.approx.ftz.f32 %0, %1;" : "=f"(r) : "f"(x));
    return r;
}
__device__ __forceinline__ uint32_t smem_u32(const void* p) {
    uint32_t a;
    asm("{ .reg .u64 t; cvta.to.shared.u64 t, %1; cvt.u32.u64 %0, t; }"
        : "=r"(a) : "l"(p));
    return a;
}

#define MMA16(d, a, b)                                                         \
    asm volatile(                                                              \
        "mma.sync.aligned.m16n8k16.row.col.f32.f16.f16.f32 "                   \
        "{%0,%1,%2,%3},{%4,%5,%6,%7},{%8,%9},{%0,%1,%2,%3};"                   \
        : "+f"((d)[0]), "+f"((d)[1]), "+f"((d)[2]), "+f"((d)[3])               \
        : "r"((a)[0]), "r"((a)[1]), "r"((a)[2]), "r"((a)[3]),                  \
          "r"((b)[0]), "r"((b)[1]))

#define LDSM4(r0, r1, r2, r3, addr)                                            \
    asm volatile("ldmatrix.sync.aligned.m8n8.x4.shared.b16 {%0,%1,%2,%3}, [%4];" \
        : "=r"(r0), "=r"(r1), "=r"(r2), "=r"(r3) : "r"(addr))

// ---------------------------------------------------------------------------
// Weight transpose + pack: W[K][N] fp32 -> WT2[n][k/2] half2
// ---------------------------------------------------------------------------
__global__ __launch_bounds__(256)
void transpose_h2(const float* __restrict__ W, uint32_t* __restrict__ WT2,
                  int K, int N)
{
    __shared__ float tile[32][33];
    const int bx = blockIdx.x;
    const int by = blockIdx.y;
    const int tx = threadIdx.x;
    const int ty = threadIdx.y;
    #pragma unroll
    for (int i = ty; i < 32; i += 8)
        tile[i][tx] = W[(size_t)(by * 32 + i) * N + bx * 32 + tx];
    __syncthreads();
    const int idx = ty * 32 + tx;
    #pragma unroll
    for (int it = 0; it < 2; it++) {
        int id = idx + it * 256;
        int nl = id >> 4;
        int kh = id & 15;
        WT2[(size_t)(bx * 32 + nl) * (K / 2) + by * 16 + kh] =
            f22h2(tile[2 * kh][nl], tile[2 * kh + 1][nl]);
    }
}

// ---------------------------------------------------------------------------
// fp16 GEMM: C = A'[M,K] @ W[K,N]; A fp32 (+pos for n<pos_ncut), W as WT2.
// 128x128x32 tile, 256 thr, warp tile 64x32. Double-buffered, reg prefetch.
// Ah/Bh rows: 32 halves (16 words) padded to 20-word stride -> ldmatrix rows
// hit bank-quads {0,20,8,28,16,4,24,12}: conflict-free. Frags via LDSM.x4.
// ---------------------------------------------------------------------------
__global__ __launch_bounds__(256, 2)
void gemm_h16(const float* __restrict__ A, const float* __restrict__ pos,
              const uint32_t* __restrict__ BT2, float* __restrict__ Cf,
              __half* __restrict__ qkh, __half* __restrict__ vT,
              int N, int K, int pos_ncut, int outmode)
{
    __shared__ uint32_t Ah[2][128 * 20];
    __shared__ uint32_t Bh[2][128 * 20];

    const int tid  = threadIdx.x;
    const int lane = tid & 31;
    const int warp = tid >> 5;
    const int wm   = warp >> 2;
    const int wn   = warp & 3;
    const int g    = lane >> 2;
    const int t    = lane & 3;

    const int m0 = blockIdx.y * 128;
    const int n0 = blockIdx.x * 128;
    const bool addpos = (pos != nullptr) && (n0 < pos_ncut);

    // ldmatrix per-lane row/chunk selectors (see theory; verified mapping)
    const int lrow  = lane & 15;                 // A row within 16
    const int lckA  = lane >> 4;                 // A k-half select
    const int lnB   = (lane & 7) + 8 * ((lane >> 4) & 1);  // B n within 16
    const int lckB  = (lane >> 3) & 1;           // B k-half select

    const uint32_t ahb0 = smem_u32(&Ah[0][0]);
    const uint32_t ahb1 = smem_u32(&Ah[1][0]);
    const uint32_t bhb0 = smem_u32(&Bh[0][0]);
    const uint32_t bhb1 = smem_u32(&Bh[1][0]);

    float4 aS[4];
    uint4  bS[2];

    auto ldg = [&](int k0) {
        #pragma unroll
        for (int it = 0; it < 2; it++) {
            int f   = tid + it * 256;
            int row = f >> 2;
            int ch  = f & 3;
            const float* ap = A + (size_t)(m0 + row) * K + k0 + ch * 8;
            float4 a0 = *(const float4*)ap;
            float4 a1 = *(const float4*)(ap + 4);
            if (addpos) {
                const float* pp = pos + (size_t)((m0 + row) & (SEQ - 1)) * K + k0 + ch * 8;
                float4 p0 = *(const float4*)pp;
                float4 p1 = *(const float4*)(pp + 4);
                a0.x += p0.x; a0.y += p0.y; a0.z += p0.z; a0.w += p0.w;
                a1.x += p1.x; a1.y += p1.y; a1.z += p1.z; a1.w += p1.w;
            }
            aS[2 * it] = a0; aS[2 * it + 1] = a1;
        }
        #pragma unroll
        for (int it = 0; it < 2; it++) {
            int f  = tid + it * 256;
            int n  = f >> 2;
            int c4 = f & 3;
            bS[it] = *(const uint4*)(BT2 + (size_t)(n0 + n) * (K / 2) + (k0 >> 1) + c4 * 4);
        }
    };
    auto sts = [&](int bf) {
        #pragma unroll
        for (int it = 0; it < 2; it++) {
            int f   = tid + it * 256;
            int row = f >> 2;
            int ch  = f & 3;
            float4 a0 = aS[2 * it], a1 = aS[2 * it + 1];
            uint4 u;
            u.x = f22h2(a0.x, a0.y); u.y = f22h2(a0.z, a0.w);
            u.z = f22h2(a1.x, a1.y); u.w = f22h2(a1.z, a1.w);
            *(uint4*)&Ah[bf][row * 20 + ch * 4] = u;
        }
        #pragma unroll
        for (int it = 0; it < 2; it++) {
            int f  = tid + it * 256;
            int n  = f >> 2;
            int c4 = f & 3;
            *(uint4*)&Bh[bf][n * 20 + c4 * 4] = bS[it];
        }
    };

    float acc[4][4][4];
    #pragma unroll
    for (int i = 0; i < 4; i++)
        #pragma unroll
        for (int j = 0; j < 4; j++)
            #pragma unroll
            for (int c = 0; c < 4; c++)
                acc[i][j][c] = 0.0f;

    ldg(0);
    sts(0);
    __syncthreads();

    int buf = 0;
    for (int k0 = 0; k0 < K; k0 += 32) {
        const bool more = (k0 + 32 < K);
        if (more) ldg(k0 + 32);

        const uint32_t ab = buf ? ahb1 : ahb0;
        const uint32_t bb = buf ? bhb1 : bhb0;

        #pragma unroll
        for (int ks = 0; ks < 2; ks++) {
            uint32_t afr[4][4], bfr[4][2];
            #pragma unroll
            for (int mi = 0; mi < 4; mi++) {
                int row = wm * 64 + mi * 16 + lrow;
                uint32_t addr = ab + (uint32_t)(row * 20 + (2 * ks + lckA) * 4) * 4;
                LDSM4(afr[mi][0], afr[mi][1], afr[mi][2], afr[mi][3], addr);
            }
            #pragma unroll
            for (int p = 0; p < 2; p++) {
                int n = wn * 32 + p * 16 + lnB;
                uint32_t addr = bb + (uint32_t)(n * 20 + (2 * ks + lckB) * 4) * 4;
                LDSM4(bfr[2 * p][0], bfr[2 * p][1],
                      bfr[2 * p + 1][0], bfr[2 * p + 1][1], addr);
            }
            #pragma unroll
            for (int mi = 0; mi < 4; mi++)
                #pragma unroll
                for (int ni = 0; ni < 4; ni++)
                    MMA16(acc[mi][ni], afr[mi], bfr[ni]);
        }

        if (more) {
            sts(buf ^ 1);
            __syncthreads();
            buf ^= 1;
        }
    }

    // ---- epilogue ----
    if (outmode == 0) {
        #pragma unroll
        for (int mi = 0; mi < 4; mi++) {
            int row = m0 + wm * 64 + mi * 16 + g;
            #pragma unroll
            for (int ni = 0; ni < 4; ni++) {
                int col = n0 + wn * 32 + ni * 8 + 2 * t;
                *(float2*)(Cf + (size_t)row * N + col) =
                    make_float2(acc[mi][ni][0], acc[mi][ni][1]);
                *(float2*)(Cf + (size_t)(row + 8) * N + col) =
                    make_float2(acc[mi][ni][2], acc[mi][ni][3]);
            }
        }
    } else if (n0 < 2048) {
        #pragma unroll
        for (int mi = 0; mi < 4; mi++) {
            int row = m0 + wm * 64 + mi * 16 + g;
            #pragma unroll
            for (int ni = 0; ni < 4; ni++) {
                int col = n0 + wn * 32 + ni * 8 + 2 * t;
                *(uint32_t*)(qkh + (size_t)row * 2048 + col) =
                    f22h2(acc[mi][ni][0], acc[mi][ni][1]);
                *(uint32_t*)(qkh + (size_t)(row + 8) * 2048 + col) =
                    f22h2(acc[mi][ni][2], acc[mi][ni][3]);
            }
        }
    } else {
        #pragma unroll
        for (int mi = 0; mi < 4; mi++) {
            int row = m0 + wm * 64 + mi * 16 + g;
            #pragma unroll
            for (int ni = 0; ni < 4; ni++) {
                int colv = n0 - 2048 + wn * 32 + ni * 8 + 2 * t;
                vT[(size_t)colv * MTOT + row]           = __float2half_rn(acc[mi][ni][0]);
                vT[(size_t)(colv + 1) * MTOT + row]     = __float2half_rn(acc[mi][ni][1]);
                vT[(size_t)colv * MTOT + row + 8]       = __float2half_rn(acc[mi][ni][2]);
                vT[(size_t)(colv + 1) * MTOT + row + 8] = __float2half_rn(acc[mi][ni][3]);
            }
        }
    }
}

// ---------------------------------------------------------------------------
// Flash attention (causal), fp16 mma + fp32 softmax, ldmatrix fragment loads.
// CTA = (b, h, 128 q-rows), 256 thr, warp owns 16 rows. Q frags in regs,
// P in regs (QK C-layout == PV A-layout). K/V double-buffered, 1 sync/tile.
// ---------------------------------------------------------------------------
#define ATTN_SMEM_BYTES (4 * 4096 * 4)   // 2 buffers x (K 4096 + V 4096) words

__global__ __launch_bounds__(256, 2)
void attn_h16(const __half* __restrict__ qkh, const __half* __restrict__ vT,
              float* __restrict__ ao)
{
    extern __shared__ uint32_t usm[];
    const uint32_t usm_u = smem_u32(usm);

    const int tid  = threadIdx.x;
    const int lane = tid & 31;
    const int warp = tid >> 5;
    const int g    = lane >> 2;
    const int t    = lane & 3;
    const int q0   = warp * 16;
    const unsigned FULL = 0xffffffffu;

    // ldmatrix per-lane selectors for B-operand loads
    const int lnB  = (lane & 7) + 8 * ((lane >> 4) & 1);
    const int lckB = (lane >> 3) & 1;

    const int bh = blockIdx.y;
    const int b  = bh >> 4;
    const int h  = bh & 15;
    const int qt = (int)gridDim.x - 1 - (int)blockIdx.x;

    // ---- Q fragments in registers (scaled by exact 0.125) ----
    uint32_t qf[4][4];
    {
        const __half* qb = qkh + (size_t)(b * SEQ + qt * 128 + q0 + g) * 2048 + h * HS;
        const __half2 s = __floats2half2_rn(0.125f, 0.125f);
        #pragma unroll
        for (int ks = 0; ks < 4; ks++) {
            __half2 v0 = *(const __half2*)(qb + ks * 16 + 2 * t);
            __half2 v1 = *(const __half2*)(qb + 8 * 2048 + ks * 16 + 2 * t);
            __half2 v2 = *(const __half2*)(qb + ks * 16 + 2 * t + 8);
            __half2 v3 = *(const __half2*)(qb + 8 * 2048 + ks * 16 + 2 * t + 8);
            v0 = __hmul2(v0, s); v1 = __hmul2(v1, s);
            v2 = __hmul2(v2, s); v3 = __hmul2(v3, s);
            qf[ks][0] = *(uint32_t*)&v0; qf[ks][1] = *(uint32_t*)&v1;
            qf[ks][2] = *(uint32_t*)&v2; qf[ks][3] = *(uint32_t*)&v3;
        }
    }

    const __half* kb0 = qkh + (size_t)(b * SEQ) * 2048 + 1024 + h * HS;
    const __half* vb0 = vT + (size_t)(h * HS) * MTOT + b * SEQ;

    auto stageK = [&](int kt2, uint32_t* Kbuf) {
        const __half* kb = kb0 + (size_t)(kt2 * 128) * 2048;
        #pragma unroll
        for (int it = 0; it < 4; it++) {
            int id  = tid + it * 256;
            int key = id >> 3;
            int ch  = id & 7;
            uint4 u = *(const uint4*)(kb + (size_t)key * 2048 + ch * 8);
            uint32_t off = ((uint32_t)key << 5) + (uint32_t)((ch ^ (key & 7)) << 2);
            *(uint4*)(Kbuf + off) = u;
        }
    };
    auto stageV = [&](int kt2, uint32_t* Vbuf) {
        const __half* vb = vb0 + kt2 * 128;
        #pragma unroll
        for (int it = 0; it < 4; it++) {
            int id = tid + it * 256;
            int d  = id >> 4;
            int ch = id & 15;
            uint4 u = *(const uint4*)(vb + (size_t)d * MTOT + ch * 8);
            *(uint4*)(Vbuf + d * 64 + ((ch ^ (d & 7)) << 2)) = u;
        }
    };

    float m0r = -1e30f, m1r = -1e30f, l0r = 0.0f, l1r = 0.0f;
    float o[8][4];
    #pragma unroll
    for (int ni = 0; ni < 8; ni++)
        o[ni][0] = o[ni][1] = o[ni][2] = o[ni][3] = 0.0f;

    const float L2E = 1.4426950408889634f;

    stageK(0, usm);
    stageV(0, usm + 4096);
    __syncthreads();

    int buf = 0;
    for (int kt = 0; kt <= qt; kt++) {
        const uint32_t kb_u = usm_u + (uint32_t)(buf * 8192) * 4;
        const uint32_t vb_u = kb_u + 4096 * 4;

        // ---- S = Q @ K^T : m16 x n128 x k64, K frags via LDSM.x4 ----
        float sacc[16][4];
        #pragma unroll
        for (int ni = 0; ni < 16; ni++)
            sacc[ni][0] = sacc[ni][1] = sacc[ni][2] = sacc[ni][3] = 0.0f;

        #pragma unroll
        for (int ks = 0; ks < 4; ks++) {
            #pragma unroll
            for (int p = 0; p < 8; p++) {
                int key = p * 16 + lnB;
                int ck  = 2 * ks + lckB;
                uint32_t addr = kb_u +
                    (uint32_t)((key << 5) + ((ck ^ (key & 7)) << 2)) * 4;
                uint32_t b0, b1, b2, b3;
                LDSM4(b0, b1, b2, b3, addr);
                uint32_t f0[2] = { b0, b1 };
                uint32_t f1[2] = { b2, b3 };
                MMA16(sacc[2 * p],     qf[ks], f0);
                MMA16(sacc[2 * p + 1], qf[ks], f1);
            }
        }

        // ---- causal mask (diagonal tile only) ----
        const int r0l = q0 + g, r1l = r0l + 8;
        if (kt == qt) {
            #pragma unroll
            for (int ni = 0; ni < 16; ni++) {
                int c = ni * 8 + 2 * t;
                if (c     > r0l) sacc[ni][0] = -1e30f;
                if (c + 1 > r0l) sacc[ni][1] = -1e30f;
                if (c     > r1l) sacc[ni][2] = -1e30f;
                if (c + 1 > r1l) sacc[ni][3] = -1e30f;
            }
        }

        // ---- row max (quad reduce) ----
        float rm0 = -1e30f, rm1 = -1e30f;
        #pragma unroll
        for (int ni = 0; ni < 16; ni++) {
            rm0 = fmaxf(rm0, fmaxf(sacc[ni][0], sacc[ni][1]));
            rm1 = fmaxf(rm1, fmaxf(sacc[ni][2], sacc[ni][3]));
        }
        rm0 = fmaxf(rm0, __shfl_xor_sync(FULL, rm0, 1));
        rm0 = fmaxf(rm0, __shfl_xor_sync(FULL, rm0, 2));
        rm1 = fmaxf(rm1, __shfl_xor_sync(FULL, rm1, 1));
        rm1 = fmaxf(rm1, __shfl_xor_sync(FULL, rm1, 2));

        float nm0 = fmaxf(m0r, rm0), nm1 = fmaxf(m1r, rm1);
        float fac0 = ex2((m0r - nm0) * L2E), fac1 = ex2((m1r - nm1) * L2E);
        float nb0 = nm0 * L2E, nb1 = nm1 * L2E;

        // ---- exp + row sums + pack P to half2 ----
        uint32_t p01[16], p23[16];
        float rs0 = 0.0f, rs1 = 0.0f;
        #pragma unroll
        for (int ni = 0; ni < 16; ni++) {
            float p00 = ex2(fmaf(sacc[ni][0], L2E, -nb0));
            float p01v = ex2(fmaf(sacc[ni][1], L2E, -nb0));
            float p10 = ex2(fmaf(sacc[ni][2], L2E, -nb1));
            float p11 = ex2(fmaf(sacc[ni][3], L2E, -nb1));
            rs0 += p00 + p01v;
            rs1 += p10 + p11;
            p01[ni] = f22h2(p00, p01v);
            p23[ni] = f22h2(p10, p11);
        }
        rs0 += __shfl_xor_sync(FULL, rs0, 1);
        rs0 += __shfl_xor_sync(FULL, rs0, 2);
        rs1 += __shfl_xor_sync(FULL, rs1, 1);
        rs1 += __shfl_xor_sync(FULL, rs1, 2);

        l0r = l0r * fac0 + rs0;
        l1r = l1r * fac1 + rs1;
        m0r = nm0; m1r = nm1;
        #pragma unroll
        for (int ni = 0; ni < 8; ni++) {
            o[ni][0] *= fac0; o[ni][1] *= fac0;
            o[ni][2] *= fac1; o[ni][3] *= fac1;
        }

        // ---- stage next K/V tile (overlaps with PV) ----
        if (kt < qt) {
            uint32_t* nb = usm + (buf ^ 1) * 8192;
            stageK(kt + 1, nb);
            stageV(kt + 1, nb + 4096);
        }

        // ---- O += P @ V : m16 x n64 x k128, V frags via LDSM.x4 ----
        #pragma unroll
        for (int kk = 0; kk < 8; kk++) {
            uint32_t afr[4] = { p01[2 * kk], p23[2 * kk],
                                p01[2 * kk + 1], p23[2 * kk + 1] };
            #pragma unroll
            for (int p = 0; p < 4; p++) {
                int d  = p * 16 + lnB;
                int ck = 2 * kk + lckB;
                uint32_t addr = vb_u +
                    (uint32_t)((d << 6) + ((ck ^ (d & 7)) << 2)) * 4;
                uint32_t b0, b1, b2, b3;
                LDSM4(b0, b1, b2, b3, addr);
                uint32_t f0[2] = { b0, b1 };
                uint32_t f1[2] = { b2, b3 };
                MMA16(o[2 * p],     afr, f0);
                MMA16(o[2 * p + 1], afr, f1);
            }
        }

        if (kt < qt) {
            __syncthreads();
            buf ^= 1;
        }
    }

    // ---- normalize + write fp32 ao ----
    float inv0 = 1.0f / l0r, inv1 = 1.0f / l1r;
    float* aobase = ao + (size_t)(b * SEQ + qt * 128) * HDIM + h * HS;
    #pragma unroll
    for (int ni = 0; ni < 8; ni++) {
        int c = ni * 8 + 2 * t;
        *(float2*)(aobase + (size_t)(q0 + g) * HDIM + c) =
            make_float2(o[ni][0] * inv0, o[ni][1] * inv0);
        *(float2*)(aobase + (size_t)(q0 + g + 8) * HDIM + c) =
            make_float2(o[ni][2] * inv1, o[ni][3] * inv1);
    }
}

// ---------------------------------------------------------------------------
extern "C" void kernel_launch(void* const* d_in, const int* in_sizes, int n_in,
                              void* d_out, int out_size)
{
    const float* x    = (const float*)d_in[0];
    const float* pos  = (const float*)d_in[1];
    const float* Wqkv = (const float*)d_in[2];
    const float* Wout = (const float*)d_in[3];
    float* out = (float*)d_out;

    float*    ao_p;
    __half *qkh_p, *vT_p;
    uint32_t *wqkvT2_p, *woutT2_p;
    cudaGetSymbolAddress((void**)&ao_p,     g_ao);
    cudaGetSymbolAddress((void**)&qkh_p,    g_qkh);
    cudaGetSymbolAddress((void**)&vT_p,     g_vT);
    cudaGetSymbolAddress((void**)&wqkvT2_p, g_wqkvT2);
    cudaGetSymbolAddress((void**)&woutT2_p, g_woutT2);

    // 0) transpose + half2-pack weights
    transpose_h2<<<dim3(N_QKV / 32, HDIM / 32), dim3(32, 8)>>>(Wqkv, wqkvT2_p, HDIM, N_QKV);
    transpose_h2<<<dim3(HDIM / 32, HDIM / 32), dim3(32, 8)>>>(Wout, woutT2_p, HDIM, HDIM);

    // 1) qkv projection -> half outputs (q|k row-major, v transposed)
    {
        dim3 grid(N_QKV / 128, MTOT / 128);
        gemm_h16<<<grid, 256>>>(x, pos, wqkvT2_p, nullptr, qkh_p, vT_p,
                                N_QKV, HDIM, 2 * HDIM, 1);
    }

    // 2) flash attention
    {
        cudaFuncSetAttribute(attn_h16,
                             cudaFuncAttributeMaxDynamicSharedMemorySize, ATTN_SMEM_BYTES);
        dim3 grid(SEQ / 128, 2 * NH);
        attn_h16<<<grid, 256, ATTN_SMEM_BYTES>>>(qkh_p, vT_p, ao_p);
    }

    // 3) out = ao @ Wout (fp32 output)
    {
        dim3 grid(HDIM / 128, MTOT / 128);
        gemm_h16<<<grid, 256>>>(ao_p, nullptr, woutT2_p, out, nullptr, nullptr,
                                HDIM, HDIM, 0, 0);
    }
}

// round 7
// speedup vs baseline: 5.9502x; 1.2181x over previous
#include <cuda_runtime.h>
#include <cuda_fp16.h>
#include <math.h>
#include <stdint.h>

#define SEQ    2048
#define HDIM   1024
#define NH     16
#define HS     64
#define MTOT   4096            // B*S
#define N_QKV  3072            // 3*HDIM

// Scratch (allocation-free rule: device globals)
__device__ __half   g_xh   [(size_t)MTOT * HDIM];        // half(x)
__device__ __half   g_xph  [(size_t)MTOT * HDIM];        // half(x+pos)
__device__ __half   g_aoh  [(size_t)MTOT * HDIM];        // attention out, half
__device__ __half   g_qkh  [(size_t)MTOT * 2048];        // q|k half row-major
__device__ __half   g_vT   [(size_t)HDIM * MTOT];        // v transposed
__device__ uint32_t g_wqkvT2[(size_t)N_QKV * (HDIM / 2)]; // W_qkv^T half2
__device__ uint32_t g_woutT2[(size_t)HDIM * (HDIM / 2)];  // W_out^T half2

// ---------------------------------------------------------------------------
// helpers
// ---------------------------------------------------------------------------
__device__ __forceinline__ uint32_t f22h2(float x, float y) {
    __half2 h = __floats2half2_rn(x, y);
    return *(uint32_t*)&h;
}
__device__ __forceinline__ float ex2(float x) {
    float r;
    asm("ex2.approx.ftz.f32 %0, %1;" : "=f"(r) : "f"(x));
    return r;
}
__device__ __forceinline__ uint32_t ex2h2(float a, float b) {
    uint32_t arg = f22h2(a, b), r;
    asm("ex2.approx.f16x2 %0, %1;" : "=r"(r) : "r"(arg));
    return r;
}
__device__ __forceinline__ uint32_t smem_u32(const void* p) {
    uint32_t a;
    asm("{ .reg .u64 t; cvta.to.shared.u64 t, %1; cvt.u32.u64 %0, t; }"
        : "=r"(a) : "l"(p));
    return a;
}

#define MMA16(d, a, b)                                                         \
    asm volatile(                                                              \
        "mma.sync.aligned.m16n8k16.row.col.f32.f16.f16.f32 "                   \
        "{%0,%1,%2,%3},{%4,%5,%6,%7},{%8,%9},{%0,%1,%2,%3};"                   \
        : "+f"((d)[0]), "+f"((d)[1]), "+f"((d)[2]), "+f"((d)[3])               \
        : "r"((a)[0]), "r"((a)[1]), "r"((a)[2]), "r"((a)[3]),                  \
          "r"((b)[0]), "r"((b)[1]))

#define LDSM4(r0, r1, r2, r3, addr)                                            \
    asm volatile("ldmatrix.sync.aligned.m8n8.x4.shared.b16 {%0,%1,%2,%3}, [%4];" \
        : "=r"(r0), "=r"(r1), "=r"(r2), "=r"(r3) : "r"(addr))

#define CP16(dst_u32, src_ptr)                                                 \
    asm volatile("cp.async.cg.shared.global [%0], [%1], 16;"                   \
        :: "r"(dst_u32), "l"(src_ptr))
#define CP_COMMIT() asm volatile("cp.async.commit_group;" ::: "memory")
#define CP_WAIT(n)  asm volatile("cp.async.wait_group %0;" :: "n"(n) : "memory")

// ---------------------------------------------------------------------------
// prep: xh = half(x), xph = half(x + pos)
// ---------------------------------------------------------------------------
__global__ __launch_bounds__(256)
void prep_x(const float* __restrict__ x, const float* __restrict__ pos,
            __half* __restrict__ xh, __half* __restrict__ xph)
{
    const int m = blockIdx.x;
    const int c = threadIdx.x * 4;
    float4 xv = *(const float4*)(x + (size_t)m * HDIM + c);
    float4 pv = *(const float4*)(pos + (size_t)(m & (SEQ - 1)) * HDIM + c);
    uint2 u0; u0.x = f22h2(xv.x, xv.y); u0.y = f22h2(xv.z, xv.w);
    *(uint2*)(xh + (size_t)m * HDIM + c) = u0;
    uint2 u1; u1.x = f22h2(xv.x + pv.x, xv.y + pv.y);
    u1.y = f22h2(xv.z + pv.z, xv.w + pv.w);
    *(uint2*)(xph + (size_t)m * HDIM + c) = u1;
}

// ---------------------------------------------------------------------------
// Weight transpose + pack: W[K][N] fp32 -> WT2[n][k/2] half2
// ---------------------------------------------------------------------------
__global__ __launch_bounds__(256)
void transpose_h2(const float* __restrict__ W, uint32_t* __restrict__ WT2,
                  int K, int N)
{
    __shared__ float tile[32][33];
    const int bx = blockIdx.x;
    const int by = blockIdx.y;
    const int tx = threadIdx.x;
    const int ty = threadIdx.y;
    #pragma unroll
    for (int i = ty; i < 32; i += 8)
        tile[i][tx] = W[(size_t)(by * 32 + i) * N + bx * 32 + tx];
    __syncthreads();
    const int idx = ty * 32 + tx;
    #pragma unroll
    for (int it = 0; it < 2; it++) {
        int id = idx + it * 256;
        int nl = id >> 4;
        int kh = id & 15;
        WT2[(size_t)(bx * 32 + nl) * (K / 2) + by * 16 + kh] =
            f22h2(tile[2 * kh][nl], tile[2 * kh + 1][nl]);
    }
}

// ---------------------------------------------------------------------------
// fp16 GEMM with half A: C = A[M,K] @ W[K,N], W as WT2[n][k/2].
// A per-CTA: A0 for n-block < ncut, else A1 (pos-add preapplied in prep).
// 128x128x32 tile, 256 thr, warp 64x32. cp.async 3-stage pipeline.
// smem rows: 32 halves (16 words) at 20-word stride -> ldmatrix conflict-free.
// ---------------------------------------------------------------------------
#define GEMM_SMEM (3 * 2560 * 2 * 4)   // 3 stages x (A 2560 + B 2560) words

__global__ __launch_bounds__(256, 2)
void gemm_h16(const __half* __restrict__ A0, const __half* __restrict__ A1,
              const uint32_t* __restrict__ BT2, float* __restrict__ Cf,
              __half* __restrict__ qkh, __half* __restrict__ vT,
              int N, int K, int ncut, int outmode)
{
    extern __shared__ uint32_t gsm[];
    const uint32_t sA_u = smem_u32(gsm);
    const uint32_t sB_u = sA_u + 3 * 2560 * 4;

    const int tid  = threadIdx.x;
    const int lane = tid & 31;
    const int warp = tid >> 5;
    const int wm   = warp >> 2;
    const int wn   = warp & 3;
    const int g    = lane >> 2;
    const int t    = lane & 3;

    const int m0 = blockIdx.y * 128;
    const int n0 = blockIdx.x * 128;
    const __half* Aptr = (n0 < ncut) ? A0 : A1;

    const int lrow = lane & 15;
    const int lckA = lane >> 4;
    const int lnB  = (lane & 7) + 8 * ((lane >> 4) & 1);
    const int lckB = (lane >> 3) & 1;

    auto stage = [&](int tt, int bf) {
        const int k0 = tt << 5;
        #pragma unroll
        for (int it = 0; it < 2; it++) {
            int id  = tid + it * 256;
            int row = id >> 2;
            int ch  = id & 3;
            CP16(sA_u + (uint32_t)(bf * 2560 + row * 20 + ch * 4) * 4,
                 Aptr + (size_t)(m0 + row) * K + k0 + ch * 8);
        }
        #pragma unroll
        for (int it = 0; it < 2; it++) {
            int id = tid + it * 256;
            int n  = id >> 2;
            int ch = id & 3;
            CP16(sB_u + (uint32_t)(bf * 2560 + n * 20 + ch * 4) * 4,
                 BT2 + (size_t)(n0 + n) * (K / 2) + (k0 >> 1) + ch * 4);
        }
    };

    float acc[4][4][4];
    #pragma unroll
    for (int i = 0; i < 4; i++)
        #pragma unroll
        for (int j = 0; j < 4; j++)
            #pragma unroll
            for (int c = 0; c < 4; c++)
                acc[i][j][c] = 0.0f;

    const int T = K >> 5;
    stage(0, 0); CP_COMMIT();
    stage(1, 1); CP_COMMIT();

    int bf = 0;
    for (int tt = 0; tt < T; tt++) {
        CP_WAIT(1);
        __syncthreads();
        if (tt + 2 < T) stage(tt + 2, (tt + 2) % 3);
        CP_COMMIT();

        const uint32_t ab = sA_u + (uint32_t)(bf * 2560) * 4;
        const uint32_t bb = sB_u + (uint32_t)(bf * 2560) * 4;
        #pragma unroll
        for (int ks = 0; ks < 2; ks++) {
            uint32_t afr[4][4], bfr[4][2];
            #pragma unroll
            for (int mi = 0; mi < 4; mi++) {
                int row = wm * 64 + mi * 16 + lrow;
                LDSM4(afr[mi][0], afr[mi][1], afr[mi][2], afr[mi][3],
                      ab + (uint32_t)(row * 20 + (2 * ks + lckA) * 4) * 4);
            }
            #pragma unroll
            for (int p = 0; p < 2; p++) {
                int n = wn * 32 + p * 16 + lnB;
                LDSM4(bfr[2 * p][0], bfr[2 * p][1],
                      bfr[2 * p + 1][0], bfr[2 * p + 1][1],
                      bb + (uint32_t)(n * 20 + (2 * ks + lckB) * 4) * 4);
            }
            #pragma unroll
            for (int mi = 0; mi < 4; mi++)
                #pragma unroll
                for (int ni = 0; ni < 4; ni++)
                    MMA16(acc[mi][ni], afr[mi], bfr[ni]);
        }
        bf = (bf + 1) % 3;
    }

    // ---- epilogue ----
    if (outmode == 0) {
        #pragma unroll
        for (int mi = 0; mi < 4; mi++) {
            int row = m0 + wm * 64 + mi * 16 + g;
            #pragma unroll
            for (int ni = 0; ni < 4; ni++) {
                int col = n0 + wn * 32 + ni * 8 + 2 * t;
                *(float2*)(Cf + (size_t)row * N + col) =
                    make_float2(acc[mi][ni][0], acc[mi][ni][1]);
                *(float2*)(Cf + (size_t)(row + 8) * N + col) =
                    make_float2(acc[mi][ni][2], acc[mi][ni][3]);
            }
        }
    } else if (n0 < 2048) {
        #pragma unroll
        for (int mi = 0; mi < 4; mi++) {
            int row = m0 + wm * 64 + mi * 16 + g;
            #pragma unroll
            for (int ni = 0; ni < 4; ni++) {
                int col = n0 + wn * 32 + ni * 8 + 2 * t;
                *(uint32_t*)(qkh + (size_t)row * 2048 + col) =
                    f22h2(acc[mi][ni][0], acc[mi][ni][1]);
                *(uint32_t*)(qkh + (size_t)(row + 8) * 2048 + col) =
                    f22h2(acc[mi][ni][2], acc[mi][ni][3]);
            }
        }
    } else {
        #pragma unroll
        for (int mi = 0; mi < 4; mi++) {
            int row = m0 + wm * 64 + mi * 16 + g;
            #pragma unroll
            for (int ni = 0; ni < 4; ni++) {
                int colv = n0 - 2048 + wn * 32 + ni * 8 + 2 * t;
                vT[(size_t)colv * MTOT + row]           = __float2half_rn(acc[mi][ni][0]);
                vT[(size_t)(colv + 1) * MTOT + row]     = __float2half_rn(acc[mi][ni][1]);
                vT[(size_t)colv * MTOT + row + 8]       = __float2half_rn(acc[mi][ni][2]);
                vT[(size_t)(colv + 1) * MTOT + row + 8] = __float2half_rn(acc[mi][ni][3]);
            }
        }
    }
}

// ---------------------------------------------------------------------------
// Flash attention (causal), fp16 mma + f16x2 exp + MMA row-sums.
// CTA = (b, h, 128 q-rows), 256 thr, warp owns 16 rows. Q/P in regs.
// K/V double-buffered via cp.async, ldmatrix fragment loads, 1 sync/tile.
// Output written as half (feeds gemm2).
// ---------------------------------------------------------------------------
#define ATTN_SMEM_BYTES (4 * 4096 * 4)

__global__ __launch_bounds__(256, 2)
void attn_h16(const __half* __restrict__ qkh, const __half* __restrict__ vT,
              __half* __restrict__ aoh)
{
    extern __shared__ uint32_t usm[];
    const uint32_t usm_u = smem_u32(usm);

    const int tid  = threadIdx.x;
    const int lane = tid & 31;
    const int warp = tid >> 5;
    const int g    = lane >> 2;
    const int t    = lane & 3;
    const int q0   = warp * 16;
    const unsigned FULL = 0xffffffffu;

    const int lnB  = (lane & 7) + 8 * ((lane >> 4) & 1);
    const int lckB = (lane >> 3) & 1;

    const int bh = blockIdx.y;
    const int b  = bh >> 4;
    const int h  = bh & 15;
    const int qt = (int)gridDim.x - 1 - (int)blockIdx.x;

    // ---- Q fragments in registers (scaled by exact 0.125) ----
    uint32_t qf[4][4];
    {
        const __half* qb = qkh + (size_t)(b * SEQ + qt * 128 + q0 + g) * 2048 + h * HS;
        const __half2 s = __floats2half2_rn(0.125f, 0.125f);
        #pragma unroll
        for (int ks = 0; ks < 4; ks++) {
            __half2 v0 = *(const __half2*)(qb + ks * 16 + 2 * t);
            __half2 v1 = *(const __half2*)(qb + 8 * 2048 + ks * 16 + 2 * t);
            __half2 v2 = *(const __half2*)(qb + ks * 16 + 2 * t + 8);
            __half2 v3 = *(const __half2*)(qb + 8 * 2048 + ks * 16 + 2 * t + 8);
            v0 = __hmul2(v0, s); v1 = __hmul2(v1, s);
            v2 = __hmul2(v2, s); v3 = __hmul2(v3, s);
            qf[ks][0] = *(uint32_t*)&v0; qf[ks][1] = *(uint32_t*)&v1;
            qf[ks][2] = *(uint32_t*)&v2; qf[ks][3] = *(uint32_t*)&v3;
        }
    }

    const __half* kb0 = qkh + (size_t)(b * SEQ) * 2048 + 1024 + h * HS;
    const __half* vb0 = vT + (size_t)(h * HS) * MTOT + b * SEQ;

    auto stageKV = [&](int kt2, int bf) {
        const uint32_t kbase = usm_u + (uint32_t)(bf * 8192) * 4;
        const __half* kb = kb0 + (size_t)(kt2 * 128) * 2048;
        #pragma unroll
        for (int it = 0; it < 4; it++) {
            int id  = tid + it * 256;
            int key = id >> 3;
            int ch  = id & 7;
            CP16(kbase + (uint32_t)(((key << 5) + ((ch ^ (key & 7)) << 2)) << 2),
                 kb + (size_t)key * 2048 + ch * 8);
        }
        const __half* vb = vb0 + kt2 * 128;
        #pragma unroll
        for (int it = 0; it < 4; it++) {
            int id = tid + it * 256;
            int d  = id >> 4;
            int ch = id & 15;
            CP16(kbase + 4096 * 4 +
                     (uint32_t)((d * 64 + ((ch ^ (d & 7)) << 2)) << 2),
                 vb + (size_t)d * MTOT + ch * 8);
        }
    };

    float m0r = -1e30f, m1r = -1e30f, l0r = 0.0f, l1r = 0.0f;
    float o[8][4];
    #pragma unroll
    for (int ni = 0; ni < 8; ni++)
        o[ni][0] = o[ni][1] = o[ni][2] = o[ni][3] = 0.0f;

    const float L2E = 1.4426950408889634f;
    const uint32_t ONES2 = 0x3C003C00u;

    stageKV(0, 0); CP_COMMIT();
    CP_WAIT(0);
    __syncthreads();

    int buf = 0;
    for (int kt = 0; kt <= qt; kt++) {
        const uint32_t kb_u = usm_u + (uint32_t)(buf * 8192) * 4;
        const uint32_t vb_u = kb_u + 4096 * 4;

        // ---- S = Q @ K^T ----
        float sacc[16][4];
        #pragma unroll
        for (int ni = 0; ni < 16; ni++)
            sacc[ni][0] = sacc[ni][1] = sacc[ni][2] = sacc[ni][3] = 0.0f;

        #pragma unroll
        for (int ks = 0; ks < 4; ks++) {
            #pragma unroll
            for (int p = 0; p < 8; p++) {
                int key = p * 16 + lnB;
                int ck  = 2 * ks + lckB;
                uint32_t addr = kb_u +
                    (uint32_t)(((key << 5) + ((ck ^ (key & 7)) << 2)) << 2);
                uint32_t b0, b1, b2, b3;
                LDSM4(b0, b1, b2, b3, addr);
                uint32_t f0[2] = { b0, b1 };
                uint32_t f1[2] = { b2, b3 };
                MMA16(sacc[2 * p],     qf[ks], f0);
                MMA16(sacc[2 * p + 1], qf[ks], f1);
            }
        }

        // ---- causal mask (diagonal tile only) ----
        const int r0l = q0 + g, r1l = r0l + 8;
        if (kt == qt) {
            #pragma unroll
            for (int ni = 0; ni < 16; ni++) {
                int c = ni * 8 + 2 * t;
                if (c     > r0l) sacc[ni][0] = -1e30f;
                if (c + 1 > r0l) sacc[ni][1] = -1e30f;
                if (c     > r1l) sacc[ni][2] = -1e30f;
                if (c + 1 > r1l) sacc[ni][3] = -1e30f;
            }
        }

        // ---- row max (quad reduce) ----
        float rm0 = -1e30f, rm1 = -1e30f;
        #pragma unroll
        for (int ni = 0; ni < 16; ni++) {
            rm0 = fmaxf(rm0, fmaxf(sacc[ni][0], sacc[ni][1]));
            rm1 = fmaxf(rm1, fmaxf(sacc[ni][2], sacc[ni][3]));
        }
        rm0 = fmaxf(rm0, __shfl_xor_sync(FULL, rm0, 1));
        rm0 = fmaxf(rm0, __shfl_xor_sync(FULL, rm0, 2));
        rm1 = fmaxf(rm1, __shfl_xor_sync(FULL, rm1, 1));
        rm1 = fmaxf(rm1, __shfl_xor_sync(FULL, rm1, 2));

        float nm0 = fmaxf(m0r, rm0), nm1 = fmaxf(m1r, rm1);
        float fac0 = ex2((m0r - nm0) * L2E), fac1 = ex2((m1r - nm1) * L2E);
        float nb0 = nm0 * L2E, nb1 = nm1 * L2E;

        // ---- exp via f16x2 MUFU: result is the packed P fragment ----
        uint32_t p01[16], p23[16];
        #pragma unroll
        for (int ni = 0; ni < 16; ni++) {
            p01[ni] = ex2h2(fmaf(sacc[ni][0], L2E, -nb0),
                            fmaf(sacc[ni][1], L2E, -nb0));
            p23[ni] = ex2h2(fmaf(sacc[ni][2], L2E, -nb1),
                            fmaf(sacc[ni][3], L2E, -nb1));
        }

        m0r = nm0; m1r = nm1;
        #pragma unroll
        for (int ni = 0; ni < 8; ni++) {
            o[ni][0] *= fac0; o[ni][1] *= fac0;
            o[ni][2] *= fac1; o[ni][3] *= fac1;
        }

        // ---- stage next K/V tile (cp.async overlaps PV) ----
        if (kt < qt) {
            stageKV(kt + 1, buf ^ 1);
            CP_COMMIT();
        }

        // ---- O += P @ V, row-sums via ones-column MMA ----
        float rsum[4] = {0.0f, 0.0f, 0.0f, 0.0f};
        #pragma unroll
        for (int kk = 0; kk < 8; kk++) {
            uint32_t afr[4] = { p01[2 * kk], p23[2 * kk],
                                p01[2 * kk + 1], p23[2 * kk + 1] };
            #pragma unroll
            for (int p = 0; p < 4; p++) {
                int d  = p * 16 + lnB;
                int ck = 2 * kk + lckB;
                uint32_t addr = vb_u +
                    (uint32_t)(((d << 6) + ((ck ^ (d & 7)) << 2)) << 2);
                uint32_t b0, b1, b2, b3;
                LDSM4(b0, b1, b2, b3, addr);
                uint32_t f0[2] = { b0, b1 };
                uint32_t f1[2] = { b2, b3 };
                MMA16(o[2 * p],     afr, f0);
                MMA16(o[2 * p + 1], afr, f1);
            }
            uint32_t of[2] = { ONES2, ONES2 };
            MMA16(rsum, afr, of);
        }

        l0r = l0r * fac0 + rsum[0];
        l1r = l1r * fac1 + rsum[2];

        if (kt < qt) {
            CP_WAIT(0);
            __syncthreads();
            buf ^= 1;
        }
    }

    // ---- normalize + write half ao ----
    float inv0 = 1.0f / l0r, inv1 = 1.0f / l1r;
    __half* aobase = aoh + (size_t)(b * SEQ + qt * 128) * HDIM + h * HS;
    #pragma unroll
    for (int ni = 0; ni < 8; ni++) {
        int c = ni * 8 + 2 * t;
        *(uint32_t*)(aobase + (size_t)(q0 + g) * HDIM + c) =
            f22h2(o[ni][0] * inv0, o[ni][1] * inv0);
        *(uint32_t*)(aobase + (size_t)(q0 + g + 8) * HDIM + c) =
            f22h2(o[ni][2] * inv1, o[ni][3] * inv1);
    }
}

// ---------------------------------------------------------------------------
extern "C" void kernel_launch(void* const* d_in, const int* in_sizes, int n_in,
                              void* d_out, int out_size)
{
    const float* x    = (const float*)d_in[0];
    const float* pos  = (const float*)d_in[1];
    const float* Wqkv = (const float*)d_in[2];
    const float* Wout = (const float*)d_in[3];
    float* out = (float*)d_out;

    __half *xh_p, *xph_p, *aoh_p, *qkh_p, *vT_p;
    uint32_t *wqkvT2_p, *woutT2_p;
    cudaGetSymbolAddress((void**)&xh_p,     g_xh);
    cudaGetSymbolAddress((void**)&xph_p,    g_xph);
    cudaGetSymbolAddress((void**)&aoh_p,    g_aoh);
    cudaGetSymbolAddress((void**)&qkh_p,    g_qkh);
    cudaGetSymbolAddress((void**)&vT_p,     g_vT);
    cudaGetSymbolAddress((void**)&wqkvT2_p, g_wqkvT2);
    cudaGetSymbolAddress((void**)&woutT2_p, g_woutT2);

    // 0) prep inputs + weights
    prep_x<<<MTOT, 256>>>(x, pos, xh_p, xph_p);
    transpose_h2<<<dim3(N_QKV / 32, HDIM / 32), dim3(32, 8)>>>(Wqkv, wqkvT2_p, HDIM, N_QKV);
    transpose_h2<<<dim3(HDIM / 32, HDIM / 32), dim3(32, 8)>>>(Wout, woutT2_p, HDIM, HDIM);

    // 1) qkv projection (half A, cp.async pipeline)
    {
        cudaFuncSetAttribute(gemm_h16,
                             cudaFuncAttributeMaxDynamicSharedMemorySize, GEMM_SMEM);
        dim3 grid(N_QKV / 128, MTOT / 128);
        gemm_h16<<<grid, 256, GEMM_SMEM>>>(xph_p, xh_p, wqkvT2_p, nullptr,
                                           qkh_p, vT_p, N_QKV, HDIM, 2048, 1);
    }

    // 2) flash attention
    {
        cudaFuncSetAttribute(attn_h16,
                             cudaFuncAttributeMaxDynamicSharedMemorySize, ATTN_SMEM_BYTES);
        dim3 grid(SEQ / 128, 2 * NH);
        attn_h16<<<grid, 256, ATTN_SMEM_BYTES>>>(qkh_p, vT_p, aoh_p);
    }

    // 3) out = ao @ Wout (fp32 output)
    {
        dim3 grid(HDIM / 128, MTOT / 128);
        gemm_h16<<<grid, 256, GEMM_SMEM>>>(aoh_p, aoh_p, woutT2_p, out,
                                           nullptr, nullptr, HDIM, HDIM, 0, 0);
    }
}